// round 6
// baseline (speedup 1.0000x reference)
#include <cuda_runtime.h>
#include <cstdint>

#define NE      20000
#define KMAX    16
#define NTRIP   (NE * KMAX)
#define EMB     128
#define INTERM  64
#define NSPH    7
#define NOUT    128
#define MT      128
#define NTHREADS 256
#define NTILES_M 157            // ceil(20000/128)
#define KSPLIT  2
#define CHUNKS  128             // chunks per CTA (half of 256 global)
#define PITCH   136             // A/B smem row pitch in floats (conflict-free)
#define PSK     100             // sumk smem per-edge pitch in floats (conflict-free)

typedef unsigned long long ull;

// ---------------- persistent device scratch ----------------
__device__ int   d_trip[NTRIP];
__device__ int   d_is64;
__device__ float d_Wimg[256 * 4096];   // 4 MB tf32 image of weight, tiled [cg][k=32][n=128]

// ---------------- helpers ----------------
__device__ __forceinline__ ull pack2(float x, float y) {
    ull r; asm("mov.b64 %0, {%1,%2};" : "=l"(r) : "f"(x), "f"(y)); return r;
}
__device__ __forceinline__ void unpack2(ull v, float& x, float& y) {
    asm("mov.b64 {%0,%1}, %2;" : "=f"(x), "=f"(y) : "l"(v));
}
__device__ __forceinline__ ull ffma2(ull a, ull b, ull c) {
    ull d; asm("fma.rn.f32x2 %0, %1, %2, %3;" : "=l"(d) : "l"(a), "l"(b), "l"(c)); return d;
}
__device__ __forceinline__ ull mul2(ull a, ull b) {
    ull d; asm("mul.rn.f32x2 %0, %1, %2;" : "=l"(d) : "l"(a), "l"(b)); return d;
}
__device__ __forceinline__ uint32_t f2tf32(float f) {
    uint32_t v; asm("cvt.rna.tf32.f32 %0, %1;" : "=r"(v) : "f"(f)); return v;
}

#define MMA_TF32(d, a, b0, b1)                                                 \
    asm volatile("mma.sync.aligned.m16n8k8.row.col.f32.tf32.tf32.f32 "         \
        "{%0,%1,%2,%3}, {%4,%5,%6,%7}, {%8,%9}, {%0,%1,%2,%3};"                \
        : "+f"((d)[0]), "+f"((d)[1]), "+f"((d)[2]), "+f"((d)[3])               \
        : "r"((a)[0]), "r"((a)[1]), "r"((a)[2]), "r"((a)[3]),                  \
          "r"(b0), "r"(b1))

// ---------------- prologue kernels ----------------
__global__ void detect_kernel(const void* idr, const void* kix, int n) {
    __shared__ int bad;
    if (threadIdx.x == 0) bad = 0;
    __syncthreads();
    int cnt = n < 2048 ? n : 2048;
    const long long* a = (const long long*)idr;
    const long long* b = (const long long*)kix;
    for (int t = threadIdx.x; t < cnt; t += blockDim.x) {
        long long v = a[t], w = b[t];
        if (v < 0 || v >= NE || w < 0 || w >= KMAX) bad = 1;
    }
    __syncthreads();
    if (threadIdx.x == 0) d_is64 = bad ? 0 : 1;
}

__global__ void build_idx_kernel(const void* idr, const void* kix, int n) {
    int t = blockIdx.x * blockDim.x + threadIdx.x;
    if (t >= n) return;
    int e, k;
    if (d_is64) {
        e = (int)((const long long*)idr)[t];
        k = (int)((const long long*)kix)[t];
    } else {
        e = ((const int*)idr)[t];
        k = ((const int*)kix)[t];
    }
    if (e >= 0 && e < NE && k >= 0 && k < KMAX) d_trip[e * KMAX + k] = t;
}

__global__ void zero_out_kernel(float* out, int n) {
    int i = blockIdx.x * blockDim.x + threadIdx.x;
    if (i < n) out[i] = 0.f;
}

// tile cg = g*64+i holds B[k=e_in 0..31][n=o 0..127] = tf32(W[g*32+e_in][i][o])
__global__ void build_wimg_kernel(const float* __restrict__ W) {
    int tile = blockIdx.x;               // 0..255
    int g = tile >> 6, i = tile & 63;
    float* dst = d_Wimg + (size_t)tile * 4096;
    #pragma unroll
    for (int j = 0; j < 16; ++j) {
        int idx = threadIdx.x + 256 * j;
        int k = idx >> 7, o = idx & 127;
        float v = W[(size_t)(g * 32 + k) * (INTERM * NOUT) + i * NOUT + o];
        dst[idx] = __uint_as_float(f2tf32(v));
    }
}

// ---------------- main fused kernel ----------------
// smem float offsets
#define F_TRIP  0                          // 2048 ints
#define F_RB0   2048                       // 896 floats
#define F_RB1   2944
#define F_SK    3840                       // 128 * PSK = 12800 floats (s=4..6 planes)
#define F_A0    (F_SK + 128 * PSK)         // 16640
#define F_A1    (F_A0 + 32 * PITCH)
#define F_B0    (F_A1 + 32 * PITCH)
#define F_B1    (F_B0 + 32 * PITCH)
#define SMEM_FLOATS (F_B1 + 32 * PITCH)    // 34048
#define SMEM_BYTES  (SMEM_FLOATS * 4)      // 136192

__global__ __launch_bounds__(NTHREADS, 1)
void fused_mma_kernel(const float* __restrict__ rbf,
                      const float* __restrict__ sph,
                      const float* __restrict__ m,
                      float* __restrict__ out) {
    extern __shared__ float sm[];
    int*   s_trip = (int*)sm;
    float* s_rb[2] = { sm + F_RB0, sm + F_RB1 };
    float* s_A[2]  = { sm + F_A0,  sm + F_A1  };
    float* s_B[2]  = { sm + F_B0,  sm + F_B1  };

    const int tid  = threadIdx.x;
    const int warp = tid >> 5, lane = tid & 31;
    const int mtile = blockIdx.x >> 1;
    const int kh    = blockIdx.x & 1;      // which K half
    const int n0    = mtile * MT;
    const int g0    = kh * 2;              // first e-group for this CTA

    // stage triplet ids (clamped)
    for (int x = tid; x < MT * KMAX; x += NTHREADS) {
        int edge = n0 + (x >> 4); if (edge >= NE) edge = NE - 1;
        int tr = d_trip[edge * KMAX + (x & 15)];
        s_trip[x] = (tr < 0) ? 0 : (tr >= NTRIP ? NTRIP - 1 : tr);
    }
    // stage rbf slice i=0 into rb[0]
    for (int x = tid; x < MT * NSPH; x += NTHREADS) {
        int e_ = x / 7, s_ = x - e_ * 7;
        int eg = n0 + e_; if (eg >= NE) eg = NE - 1;
        s_rb[0][x] = rbf[(size_t)eg * (INTERM * NSPH) + s_];
    }
    __syncthreads();

    // per-thread identity for A production: edge n (0..127), e-half h (0..1)
    const int n = tid & 127, h = tid >> 7;
    int nglob = n0 + n; if (nglob >= NE) nglob = NE - 1;

    // sumk: s=0..3 in registers (persistent), s=4..6 in smem (thread-private region)
    ull sk[4][8];
    float* mysk = sm + F_SK + n * PSK + h * 16;   // [s'][16e] planes at +s'*32

    auto phase1 = [&](int g) {
        ull tmp[NSPH][8];
        #pragma unroll
        for (int s = 0; s < NSPH; ++s)
            #pragma unroll
            for (int ep = 0; ep < 8; ++ep) tmp[s][ep] = 0ULL;
        const int ebase = g * 32 + h * 16;
        #pragma unroll
        for (int k = 0; k < KMAX; ++k) {
            const float4* mr = (const float4*)(m + (size_t)s_trip[n * KMAX + k] * EMB + ebase);
            float4 m0 = mr[0], m1 = mr[1], m2 = mr[2], m3 = mr[3];
            ull mp[8];
            mp[0] = pack2(m0.x, m0.y); mp[1] = pack2(m0.z, m0.w);
            mp[2] = pack2(m1.x, m1.y); mp[3] = pack2(m1.z, m1.w);
            mp[4] = pack2(m2.x, m2.y); mp[5] = pack2(m2.z, m2.w);
            mp[6] = pack2(m3.x, m3.y); mp[7] = pack2(m3.z, m3.w);
            const float* sp = sph + (size_t)nglob * (NSPH * KMAX) + k;
            #pragma unroll
            for (int s = 0; s < NSPH; ++s) {
                float sv = sp[s * KMAX];
                ull s2 = pack2(sv, sv);
                #pragma unroll
                for (int ep = 0; ep < 8; ++ep) tmp[s][ep] = ffma2(s2, mp[ep], tmp[s][ep]);
            }
        }
        // keep s=0..3 in regs
        #pragma unroll
        for (int s = 0; s < 4; ++s)
            #pragma unroll
            for (int ep = 0; ep < 8; ++ep) sk[s][ep] = tmp[s][ep];
        // park s=4..6 in smem (own region; no other thread touches it)
        #pragma unroll
        for (int s2 = 0; s2 < 3; ++s2) {
            ull* dst = (ull*)(mysk + s2 * 32);
            #pragma unroll
            for (int ep = 0; ep < 8; ++ep) dst[ep] = tmp[4 + s2][ep];
        }
    };

    // prepare chunk cn: build A,B into buffer cn&1; stage rbf for i(cn+1)
    auto prepare = [&](int cn) {
        if (cn > 0 && (cn & 63) == 0) phase1(g0 + (cn >> 6));
        const int p = cn & 1;
        float* As = s_A[p];
        float* Bs = s_B[p];
        // phase 2: A[k][n] tf32, k = h*16 + (0..15)
        {
            const float* rb = s_rb[p] + n * NSPH;
            float rv[NSPH];
            #pragma unroll
            for (int s = 0; s < NSPH; ++s) rv[s] = rb[s];
            ull a2[8];
            {
                ull r0 = pack2(rv[0], rv[0]);
                #pragma unroll
                for (int ep = 0; ep < 8; ++ep) a2[ep] = mul2(r0, sk[0][ep]);
            }
            #pragma unroll
            for (int s = 1; s < 4; ++s) {
                ull rr = pack2(rv[s], rv[s]);
                #pragma unroll
                for (int ep = 0; ep < 8; ++ep) a2[ep] = ffma2(rr, sk[s][ep], a2[ep]);
            }
            #pragma unroll
            for (int s2 = 0; s2 < 3; ++s2) {
                const ull* w = (const ull*)(mysk + s2 * 32);
                ull rr = pack2(rv[4 + s2], rv[4 + s2]);
                #pragma unroll
                for (int ep = 0; ep < 8; ++ep) a2[ep] = ffma2(rr, w[ep], a2[ep]);
            }
            #pragma unroll
            for (int ep = 0; ep < 8; ++ep) {
                float f0, f1; unpack2(a2[ep], f0, f1);
                int k = h * 16 + 2 * ep;
                As[k * PITCH + n]       = __uint_as_float(f2tf32(f0));
                As[(k + 1) * PITCH + n] = __uint_as_float(f2tf32(f1));
            }
        }
        // B tile copy (tf32 image, gmem->smem with pitch)
        {
            const int cg = kh * CHUNKS + cn;
            const float4* src = (const float4*)(d_Wimg + (size_t)cg * 4096);
            #pragma unroll
            for (int j = 0; j < 4; ++j) {
                int fidx = tid + 256 * j;
                int row = fidx >> 5, c4 = fidx & 31;
                *(float4*)(Bs + row * PITCH + c4 * 4) = src[fidx];
            }
        }
        // stage rbf for chunk cn+1 (slice i = (cn+1)&63) into rb[(cn+1)&1]
        {
            const int ni = (cn + 1) & 63;
            float* buf = s_rb[(cn + 1) & 1];
            for (int x = tid; x < MT * NSPH; x += NTHREADS) {
                int e_ = x / 7, s_ = x - e_ * 7;
                int eg = n0 + e_; if (eg >= NE) eg = NE - 1;
                buf[x] = rbf[(size_t)eg * (INTERM * NSPH) + ni * NSPH + s_];
            }
        }
    };

    phase1(g0);
    prepare(0);

    // ---- mma mainloop ----
    const int wm = (warp >> 2) * 64, wn = (warp & 3) * 32;
    const int q = lane >> 2, r = lane & 3;

    float acc[4][4][4];
    #pragma unroll
    for (int mi = 0; mi < 4; ++mi)
        #pragma unroll
        for (int ni = 0; ni < 4; ++ni)
            #pragma unroll
            for (int v = 0; v < 4; ++v) acc[mi][ni][v] = 0.f;

    for (int c = 0; c < CHUNKS; ++c) {
        __syncthreads();
        const uint32_t* Au = (const uint32_t*)s_A[c & 1];
        const uint32_t* Bu = (const uint32_t*)s_B[c & 1];
        #pragma unroll
        for (int ks = 0; ks < 4; ++ks) {
            const int kb = ks * 8;
            uint32_t a[4][4];
            #pragma unroll
            for (int mi = 0; mi < 4; ++mi) {
                int base = (kb + r) * PITCH + wm + mi * 16 + q;
                a[mi][0] = Au[base];
                a[mi][1] = Au[base + 8];
                a[mi][2] = Au[base + 4 * PITCH];
                a[mi][3] = Au[base + 4 * PITCH + 8];
            }
            #pragma unroll
            for (int ni = 0; ni < 4; ++ni) {
                uint32_t b0 = Bu[(kb + r) * PITCH + wn + ni * 8 + q];
                uint32_t b1 = Bu[(kb + r + 4) * PITCH + wn + ni * 8 + q];
                #pragma unroll
                for (int mi = 0; mi < 4; ++mi)
                    MMA_TF32(acc[mi][ni], a[mi], b0, b1);
            }
        }
        if (c < CHUNKS - 1) prepare(c + 1);
    }

    // ---- epilogue: atomic add partial (split-K) ----
    #pragma unroll
    for (int mi = 0; mi < 4; ++mi) {
        int row0 = n0 + wm + mi * 16 + q;
        int row1 = row0 + 8;
        #pragma unroll
        for (int ni = 0; ni < 4; ++ni) {
            int col = wn + ni * 8 + 2 * r;
            if (row0 < NE) {
                atomicAdd(&out[(size_t)row0 * NOUT + col],     acc[mi][ni][0]);
                atomicAdd(&out[(size_t)row0 * NOUT + col + 1], acc[mi][ni][1]);
            }
            if (row1 < NE) {
                atomicAdd(&out[(size_t)row1 * NOUT + col],     acc[mi][ni][2]);
                atomicAdd(&out[(size_t)row1 * NOUT + col + 1], acc[mi][ni][3]);
            }
        }
    }
}

extern "C" void kernel_launch(void* const* d_in, const int* in_sizes, int n_in,
                              void* d_out, int out_size) {
    const float *rbf = 0, *sph = 0, *m = 0, *weight = 0;
    const void *idr = 0, *kix = 0;
    for (int i = 0; i < n_in; ++i) {
        long long sz = in_sizes[i];
        if      (sz == (long long)NE * INTERM * NSPH)  rbf = (const float*)d_in[i];
        else if (sz == (long long)NE * NSPH * KMAX)    sph = (const float*)d_in[i];
        else if (sz == (long long)NTRIP * EMB)         m = (const float*)d_in[i];
        else if (sz == (long long)EMB * INTERM * NOUT) weight = (const float*)d_in[i];
        else if (sz == (long long)NTRIP) { if (!idr) idr = d_in[i]; else kix = d_in[i]; }
    }
    float* out = (float*)d_out;

    cudaFuncSetAttribute(fused_mma_kernel,
                         cudaFuncAttributeMaxDynamicSharedMemorySize, SMEM_BYTES);

    zero_out_kernel<<<(NE * NOUT + 255) / 256, 256>>>(out, NE * NOUT);
    detect_kernel<<<1, 256>>>(idr, kix, NTRIP);
    build_idx_kernel<<<(NTRIP + 255) / 256, 256>>>(idr, kix, NTRIP);
    build_wimg_kernel<<<256, 256>>>(weight);
    fused_mma_kernel<<<NTILES_M * KSPLIT, NTHREADS, SMEM_BYTES>>>(rbf, sph, m, out);
}

// round 7
// speedup vs baseline: 1.6502x; 1.6502x over previous
#include <cuda_runtime.h>
#include <cstdint>

#define NE      20000
#define KMAX    16
#define NTRIP   (NE * KMAX)
#define EMB     128
#define INTERM  64
#define NSPH    7
#define NOUT    128
#define MT      128
#define NTHREADS 512
#define NTILES_M 157
#define KSPLIT  2
#define CHUNKS  128             // chunks per CTA (K=32 each; half of 256 global)
#define PITCH   136             // A/B smem row pitch in floats (conflict-free)

typedef unsigned long long ull;

// ---------------- persistent device scratch ----------------
__device__ int   d_trip[NTRIP];
__device__ int   d_is64;
__device__ float d_Wimg[256 * 4096];   // 4 MB tf32 image of weight, tiled [cg][k=32][n=128]

// ---------------- helpers ----------------
__device__ __forceinline__ uint32_t smem_u32(const void* p) {
    uint32_t a;
    asm("{ .reg .u64 t; cvta.to.shared.u64 t, %1; cvt.u32.u64 %0, t; }" : "=r"(a) : "l"(p));
    return a;
}
__device__ __forceinline__ ull pack2(float x, float y) {
    ull r; asm("mov.b64 %0, {%1,%2};" : "=l"(r) : "f"(x), "f"(y)); return r;
}
__device__ __forceinline__ void unpack2(ull v, float& x, float& y) {
    asm("mov.b64 {%0,%1}, %2;" : "=f"(x), "=f"(y) : "l"(v));
}
__device__ __forceinline__ ull ffma2(ull a, ull b, ull c) {
    ull d; asm("fma.rn.f32x2 %0, %1, %2, %3;" : "=l"(d) : "l"(a), "l"(b), "l"(c)); return d;
}
__device__ __forceinline__ ull mul2(ull a, ull b) {
    ull d; asm("mul.rn.f32x2 %0, %1, %2;" : "=l"(d) : "l"(a), "l"(b)); return d;
}
__device__ __forceinline__ uint32_t f2tf32(float f) {
    uint32_t v; asm("cvt.rna.tf32.f32 %0, %1;" : "=r"(v) : "f"(f)); return v;
}
__device__ __forceinline__ void cp_async16(uint32_t dst, const void* src) {
    asm volatile("cp.async.cg.shared.global [%0], [%1], 16;" :: "r"(dst), "l"(src) : "memory");
}
#define CP_COMMIT() asm volatile("cp.async.commit_group;" ::: "memory")
#define CP_WAIT0()  asm volatile("cp.async.wait_group 0;" ::: "memory")

#define MMA_TF32(d, a, b0, b1)                                                 \
    asm volatile("mma.sync.aligned.m16n8k8.row.col.f32.tf32.tf32.f32 "         \
        "{%0,%1,%2,%3}, {%4,%5,%6,%7}, {%8,%9}, {%0,%1,%2,%3};"                \
        : "+f"((d)[0]), "+f"((d)[1]), "+f"((d)[2]), "+f"((d)[3])               \
        : "r"((a)[0]), "r"((a)[1]), "r"((a)[2]), "r"((a)[3]),                  \
          "r"(b0), "r"(b1))

// ---------------- prologue kernels ----------------
__global__ void detect_kernel(const void* idr, const void* kix, int n) {
    __shared__ int bad;
    if (threadIdx.x == 0) bad = 0;
    __syncthreads();
    int cnt = n < 2048 ? n : 2048;
    const long long* a = (const long long*)idr;
    const long long* b = (const long long*)kix;
    for (int t = threadIdx.x; t < cnt; t += blockDim.x) {
        long long v = a[t], w = b[t];
        if (v < 0 || v >= NE || w < 0 || w >= KMAX) bad = 1;
    }
    __syncthreads();
    if (threadIdx.x == 0) d_is64 = bad ? 0 : 1;
}

__global__ void build_idx_kernel(const void* idr, const void* kix, int n) {
    int t = blockIdx.x * blockDim.x + threadIdx.x;
    if (t >= n) return;
    int e, k;
    if (d_is64) {
        e = (int)((const long long*)idr)[t];
        k = (int)((const long long*)kix)[t];
    } else {
        e = ((const int*)idr)[t];
        k = ((const int*)kix)[t];
    }
    if (e >= 0 && e < NE && k >= 0 && k < KMAX) d_trip[e * KMAX + k] = t;
}

// merged: blocks [0,256) build Wimg tiles; blocks [256, 256+2500) zero out
__global__ void prep_kernel(const float* __restrict__ W, float* __restrict__ out) {
    int bid = blockIdx.x;
    if (bid < 256) {
        int g = bid >> 6, i = bid & 63;
        float* dst = d_Wimg + (size_t)bid * 4096;
        #pragma unroll
        for (int j = 0; j < 16; ++j) {
            int idx = threadIdx.x + 256 * j;
            int k = idx >> 7, o = idx & 127;
            float v = W[(size_t)(g * 32 + k) * (INTERM * NOUT) + i * NOUT + o];
            dst[idx] = __uint_as_float(f2tf32(v));
        }
    } else {
        int i = (bid - 256) * 256 + threadIdx.x;   // float4 index
        if (i < NE * NOUT / 4)
            ((float4*)out)[i] = make_float4(0.f, 0.f, 0.f, 0.f);
    }
}

// ---------------- main fused kernel ----------------
// smem float offsets
#define F_TRIP  0                          // 2048 ints
#define F_RB    2048                       // 3 x 896 floats
#define F_SK    4736                       // 512 * 26 = 13312 floats (s=4..6 planes)
#define F_A0    18048
#define F_A1    (F_A0 + 32 * PITCH)
#define F_B0    (F_A1 + 32 * PITCH)
#define F_B1    (F_B0 + 32 * PITCH)
#define SMEM_FLOATS (F_B1 + 32 * PITCH)    // 35456
#define SMEM_BYTES  (SMEM_FLOATS * 4)      // 141824

__global__ __launch_bounds__(NTHREADS, 1)
void fused_mma_kernel(const float* __restrict__ rbf,
                      const float* __restrict__ sph,
                      const float* __restrict__ m,
                      float* __restrict__ out) {
    extern __shared__ float sm[];
    int*   s_trip = (int*)sm;

    const int tid  = threadIdx.x;
    const int warp = tid >> 5, lane = tid & 31;
    const int mtile = blockIdx.x >> 1;
    const int kh    = blockIdx.x & 1;      // which K half
    const int n0    = mtile * MT;
    const int g0    = kh * 2;              // first e-group for this CTA

    // stage triplet ids (clamped)
    for (int x = tid; x < MT * KMAX; x += NTHREADS) {
        int edge = n0 + (x >> 4); if (edge >= NE) edge = NE - 1;
        int tr = d_trip[edge * KMAX + (x & 15)];
        s_trip[x] = (tr < 0) ? 0 : (tr >= NTRIP ? NTRIP - 1 : tr);
    }
    // stage rbf slices i=0,1 into rb[0],rb[1]
    #pragma unroll
    for (int j = 0; j < 2; ++j) {
        float* buf = sm + F_RB + j * 896;
        for (int x = tid; x < MT * NSPH; x += NTHREADS) {
            int e_ = x / 7, s_ = x - e_ * 7;
            int eg = n0 + e_; if (eg >= NE) eg = NE - 1;
            buf[x] = rbf[(size_t)eg * (INTERM * NSPH) + j * NSPH + s_];
        }
    }
    __syncthreads();

    // per-thread identity for A production: edge n (0..127), e-octet h (0..3)
    const int n = tid & 127, h = tid >> 7;
    int nglob = n0 + n; if (nglob >= NE) nglob = NE - 1;

    // sumk: s=0..3 in registers, s=4..6 in private smem region (4 ull per plane)
    ull sk[4][4];
    ull* myskp = (ull*)(sm + F_SK) + tid * 13;   // planes at +0,+4,+8

    auto phase1 = [&](int g) {
        ull t3[3][4];
        #pragma unroll
        for (int s = 0; s < 4; ++s)
            #pragma unroll
            for (int ep = 0; ep < 4; ++ep) sk[s][ep] = 0ULL;
        #pragma unroll
        for (int s = 0; s < 3; ++s)
            #pragma unroll
            for (int ep = 0; ep < 4; ++ep) t3[s][ep] = 0ULL;
        const int ebase = g * 32 + h * 8;
        #pragma unroll
        for (int k = 0; k < KMAX; ++k) {
            const float4* mr = (const float4*)(m + (size_t)s_trip[n * KMAX + k] * EMB + ebase);
            float4 m0 = mr[0], m1 = mr[1];
            ull mp[4];
            mp[0] = pack2(m0.x, m0.y); mp[1] = pack2(m0.z, m0.w);
            mp[2] = pack2(m1.x, m1.y); mp[3] = pack2(m1.z, m1.w);
            const float* sp = sph + (size_t)nglob * (NSPH * KMAX) + k;
            #pragma unroll
            for (int s = 0; s < 4; ++s) {
                float sv = sp[s * KMAX];
                ull s2 = pack2(sv, sv);
                #pragma unroll
                for (int ep = 0; ep < 4; ++ep) sk[s][ep] = ffma2(s2, mp[ep], sk[s][ep]);
            }
            #pragma unroll
            for (int s = 0; s < 3; ++s) {
                float sv = sp[(4 + s) * KMAX];
                ull s2 = pack2(sv, sv);
                #pragma unroll
                for (int ep = 0; ep < 4; ++ep) t3[s][ep] = ffma2(s2, mp[ep], t3[s][ep]);
            }
        }
        #pragma unroll
        for (int s = 0; s < 3; ++s)
            #pragma unroll
            for (int ep = 0; ep < 4; ++ep) myskp[s * 4 + ep] = t3[s][ep];
    };

    // build A for chunk cn into buffer (cn&1): rows k = h*8 + (0..7)
    auto buildA = [&](int cn) {
        float* As = sm + ((cn & 1) ? F_A1 : F_A0);
        const float* rb = sm + F_RB + (cn % 3) * 896 + n * NSPH;
        float rv[NSPH];
        #pragma unroll
        for (int s = 0; s < NSPH; ++s) rv[s] = rb[s];
        ull a2[4];
        {
            ull r0 = pack2(rv[0], rv[0]);
            #pragma unroll
            for (int ep = 0; ep < 4; ++ep) a2[ep] = mul2(r0, sk[0][ep]);
        }
        #pragma unroll
        for (int s = 1; s < 4; ++s) {
            ull rr = pack2(rv[s], rv[s]);
            #pragma unroll
            for (int ep = 0; ep < 4; ++ep) a2[ep] = ffma2(rr, sk[s][ep], a2[ep]);
        }
        #pragma unroll
        for (int s = 0; s < 3; ++s) {
            ull rr = pack2(rv[4 + s], rv[4 + s]);
            #pragma unroll
            for (int ep = 0; ep < 4; ++ep) a2[ep] = ffma2(rr, myskp[s * 4 + ep], a2[ep]);
        }
        #pragma unroll
        for (int ep = 0; ep < 4; ++ep) {
            float f0, f1; unpack2(a2[ep], f0, f1);
            int k = h * 8 + 2 * ep;
            As[k * PITCH + n]       = __uint_as_float(f2tf32(f0));
            As[(k + 1) * PITCH + n] = __uint_as_float(f2tf32(f1));
        }
    };

    // async B copy for chunk cn into buffer (cn&1): 2 float4 per thread
    auto copyB = [&](int cn) {
        const int cg = kh * CHUNKS + cn;
        const float* src = d_Wimg + (size_t)cg * 4096;
        uint32_t Bs = smem_u32(sm + ((cn & 1) ? F_B1 : F_B0));
        #pragma unroll
        for (int j = 0; j < 2; ++j) {
            int fidx = tid + 512 * j;
            int row = fidx >> 5, c4 = fidx & 31;
            cp_async16(Bs + (row * PITCH + c4 * 4) * 4, src + fidx * 4);
        }
        CP_COMMIT();
    };

    // stage rbf slice for chunk cn into rb[cn%3]
    auto stageRb = [&](int cn) {
        const int i = cn & 63;
        float* buf = sm + F_RB + (cn % 3) * 896;
        for (int x = tid; x < MT * NSPH; x += NTHREADS) {
            int e_ = x / 7, s_ = x - e_ * 7;
            int eg = n0 + e_; if (eg >= NE) eg = NE - 1;
            buf[x] = rbf[(size_t)eg * (INTERM * NSPH) + i * NSPH + s_];
        }
    };

    phase1(g0);
    buildA(0);
    copyB(0);
    CP_WAIT0();
    __syncthreads();

    // ---- mma mainloop ----
    const int wm = (warp >> 2) * 32, wn = (warp & 3) * 32;
    const int q = lane >> 2, r = lane & 3;

    float acc[2][4][4];
    #pragma unroll
    for (int mi = 0; mi < 2; ++mi)
        #pragma unroll
        for (int ni = 0; ni < 4; ++ni)
            #pragma unroll
            for (int v = 0; v < 4; ++v) acc[mi][ni][v] = 0.f;

    for (int c = 0; c < CHUNKS; ++c) {
        const int p = c & 1;
        if (c + 1 < CHUNKS) copyB(c + 1);
        if (c + 2 < CHUNKS) stageRb(c + 2);
        if (c == 63) phase1(g0 + 1);

        const uint32_t* Au = (const uint32_t*)(sm + (p ? F_A1 : F_A0));
        const uint32_t* Bu = (const uint32_t*)(sm + (p ? F_B1 : F_B0));
        #pragma unroll
        for (int ks = 0; ks < 4; ++ks) {
            const int kb = ks * 8;
            uint32_t a[2][4];
            #pragma unroll
            for (int mi = 0; mi < 2; ++mi) {
                int base = (kb + r) * PITCH + wm + mi * 16 + q;
                a[mi][0] = Au[base];
                a[mi][1] = Au[base + 8];
                a[mi][2] = Au[base + 4 * PITCH];
                a[mi][3] = Au[base + 4 * PITCH + 8];
            }
            #pragma unroll
            for (int ni = 0; ni < 4; ++ni) {
                uint32_t b0 = Bu[(kb + r) * PITCH + wn + ni * 8 + q];
                uint32_t b1 = Bu[(kb + r + 4) * PITCH + wn + ni * 8 + q];
                #pragma unroll
                for (int mi = 0; mi < 2; ++mi)
                    MMA_TF32(acc[mi][ni], a[mi], b0, b1);
            }
        }

        if (c + 1 < CHUNKS) buildA(c + 1);
        CP_WAIT0();
        __syncthreads();
    }

    // ---- epilogue: atomic add partial (split-K) ----
    #pragma unroll
    for (int mi = 0; mi < 2; ++mi) {
        int row0 = n0 + wm + mi * 16 + q;
        int row1 = row0 + 8;
        #pragma unroll
        for (int ni = 0; ni < 4; ++ni) {
            int col = wn + ni * 8 + 2 * r;
            if (row0 < NE) {
                atomicAdd(&out[(size_t)row0 * NOUT + col],     acc[mi][ni][0]);
                atomicAdd(&out[(size_t)row0 * NOUT + col + 1], acc[mi][ni][1]);
            }
            if (row1 < NE) {
                atomicAdd(&out[(size_t)row1 * NOUT + col],     acc[mi][ni][2]);
                atomicAdd(&out[(size_t)row1 * NOUT + col + 1], acc[mi][ni][3]);
            }
        }
    }
}

extern "C" void kernel_launch(void* const* d_in, const int* in_sizes, int n_in,
                              void* d_out, int out_size) {
    const float *rbf = 0, *sph = 0, *m = 0, *weight = 0;
    const void *idr = 0, *kix = 0;
    for (int i = 0; i < n_in; ++i) {
        long long sz = in_sizes[i];
        if      (sz == (long long)NE * INTERM * NSPH)  rbf = (const float*)d_in[i];
        else if (sz == (long long)NE * NSPH * KMAX)    sph = (const float*)d_in[i];
        else if (sz == (long long)NTRIP * EMB)         m = (const float*)d_in[i];
        else if (sz == (long long)EMB * INTERM * NOUT) weight = (const float*)d_in[i];
        else if (sz == (long long)NTRIP) { if (!idr) idr = d_in[i]; else kix = d_in[i]; }
    }
    float* out = (float*)d_out;

    cudaFuncSetAttribute(fused_mma_kernel,
                         cudaFuncAttributeMaxDynamicSharedMemorySize, SMEM_BYTES);

    detect_kernel<<<1, 256>>>(idr, kix, NTRIP);
    build_idx_kernel<<<(NTRIP + 255) / 256, 256>>>(idr, kix, NTRIP);
    prep_kernel<<<256 + (NE * NOUT / 4 + 255) / 256, 256>>>(weight, out);
    fused_mma_kernel<<<NTILES_M * KSPLIT, NTHREADS, SMEM_BYTES>>>(rbf, sph, m, out);
}

// round 8
// speedup vs baseline: 2.1864x; 1.3249x over previous
#include <cuda_runtime.h>
#include <cstdint>

#define NE      20000
#define KMAX    16
#define NTRIP   (NE * KMAX)
#define EMB     128
#define INTERM  64
#define NSPH    7
#define NOUT    128
#define MT      128
#define NTHREADS 512
#define NTILES_M 157
#define KSPLIT  2
#define CHUNKS  128             // per CTA; chunk = 2 i-values x 16 e  (K=32)
#define PITCH   136             // A/B smem row pitch (floats)
#define SPH_P   113             // sph smem pitch (floats), coprime with 32

typedef unsigned long long ull;

// ---------------- persistent device scratch ----------------
__device__ int   d_trip[NTRIP];
__device__ int   d_is64;
__device__ float d_Wimg[256 * 4096];            // tf32 B tiles, new K-order
__device__ float d_rbfT[INTERM * NSPH * NE];    // rbf transposed [i][s][e]

// ---------------- helpers ----------------
__device__ __forceinline__ uint32_t smem_u32(const void* p) {
    uint32_t a;
    asm("{ .reg .u64 t; cvta.to.shared.u64 t, %1; cvt.u32.u64 %0, t; }" : "=r"(a) : "l"(p));
    return a;
}
__device__ __forceinline__ ull pack2(float x, float y) {
    ull r; asm("mov.b64 %0, {%1,%2};" : "=l"(r) : "f"(x), "f"(y)); return r;
}
__device__ __forceinline__ void unpack2(ull v, float& x, float& y) {
    asm("mov.b64 {%0,%1}, %2;" : "=f"(x), "=f"(y) : "l"(v));
}
__device__ __forceinline__ ull ffma2(ull a, ull b, ull c) {
    ull d; asm("fma.rn.f32x2 %0, %1, %2, %3;" : "=l"(d) : "l"(a), "l"(b), "l"(c)); return d;
}
__device__ __forceinline__ ull mul2(ull a, ull b) {
    ull d; asm("mul.rn.f32x2 %0, %1, %2;" : "=l"(d) : "l"(a), "l"(b)); return d;
}
__device__ __forceinline__ uint32_t f2tf32(float f) {
    uint32_t v; asm("cvt.rna.tf32.f32 %0, %1;" : "=r"(v) : "f"(f)); return v;
}
__device__ __forceinline__ void cp_async16(uint32_t dst, const void* src) {
    asm volatile("cp.async.cg.shared.global [%0], [%1], 16;" :: "r"(dst), "l"(src) : "memory");
}
#define CP_COMMIT() asm volatile("cp.async.commit_group;" ::: "memory")
#define CP_WAIT0()  asm volatile("cp.async.wait_group 0;" ::: "memory")

#define MMA_TF32(d, a, b0, b1)                                                 \
    asm volatile("mma.sync.aligned.m16n8k8.row.col.f32.tf32.tf32.f32 "         \
        "{%0,%1,%2,%3}, {%4,%5,%6,%7}, {%8,%9}, {%0,%1,%2,%3};"                \
        : "+f"((d)[0]), "+f"((d)[1]), "+f"((d)[2]), "+f"((d)[3])               \
        : "r"((a)[0]), "r"((a)[1]), "r"((a)[2]), "r"((a)[3]),                  \
          "r"(b0), "r"(b1))

// ---------------- prologue kernels ----------------
__global__ void detect_kernel(const void* idr, const void* kix, int n) {
    __shared__ int bad;
    if (threadIdx.x == 0) bad = 0;
    __syncthreads();
    int cnt = n < 2048 ? n : 2048;
    const long long* a = (const long long*)idr;
    const long long* b = (const long long*)kix;
    for (int t = threadIdx.x; t < cnt; t += blockDim.x) {
        long long v = a[t], w = b[t];
        if (v < 0 || v >= NE || w < 0 || w >= KMAX) bad = 1;
    }
    __syncthreads();
    if (threadIdx.x == 0) d_is64 = bad ? 0 : 1;
}

__global__ void build_idx_kernel(const void* idr, const void* kix, int n) {
    int t = blockIdx.x * blockDim.x + threadIdx.x;
    if (t >= n) return;
    int e, k;
    if (d_is64) {
        e = (int)((const long long*)idr)[t];
        k = (int)((const long long*)kix)[t];
    } else {
        e = ((const int*)idr)[t];
        k = ((const int*)kix)[t];
    }
    if (e >= 0 && e < NE && k >= 0 && k < KMAX) d_trip[e * KMAX + k] = t;
}

// blocks [0,256): Wimg tiles (new K-order)
// blocks [256, 256+2188): rbfT transpose
// blocks [256+2188, +2500): zero out
#define NB_WIMG 256
#define NB_RBFT 2188
#define NB_ZERO 2500
__global__ void prep_kernel(const float* __restrict__ W,
                            const float* __restrict__ rbf,
                            float* __restrict__ out) {
    int bid = blockIdx.x;
    if (bid < NB_WIMG) {
        // chunk cg: kh = cg>>7, c = cg&127, g = kh*4 + (c>>5), j = c&31
        // row k: e = g*16 + (k&15), i = 2*j + (k>>4)
        int cg = bid;
        int kh = cg >> 7, c = cg & 127;
        int g = kh * 4 + (c >> 5), j = c & 31;
        float* dst = d_Wimg + (size_t)cg * 4096;
        #pragma unroll
        for (int jj = 0; jj < 16; ++jj) {
            int idx = threadIdx.x + 256 * jj;
            int k = idx >> 7, o = idx & 127;
            int e = g * 16 + (k & 15);
            int i = 2 * j + (k >> 4);
            float v = W[(size_t)e * (INTERM * NOUT) + i * NOUT + o];
            dst[idx] = __uint_as_float(f2tf32(v));
        }
    } else if (bid < NB_WIMG + NB_RBFT) {
        // d_rbfT[(i*7+s)*NE + e] = rbf[e*448 + i*7 + s]
        int base = (bid - NB_WIMG) * 4096;
        #pragma unroll
        for (int jj = 0; jj < 16; ++jj) {
            int idx = base + jj * 256 + threadIdx.x;
            if (idx < INTERM * NSPH * NE) {
                int row = idx / NE, e = idx - row * NE;
                d_rbfT[idx] = rbf[(size_t)e * (INTERM * NSPH) + row];
            }
        }
    } else {
        int i = (bid - NB_WIMG - NB_RBFT) * 256 + threadIdx.x;
        if (i < NE * NOUT / 4)
            ((float4*)out)[i] = make_float4(0.f, 0.f, 0.f, 0.f);
    }
}

// ---------------- main fused kernel ----------------
// smem float offsets
#define F_TRIP  0                          // 2048 ints
#define F_SPH   2048                       // 128*113 = 14464
#define F_RB    16512                      // 2 x 14 x 128 = 3584
#define F_A0    20096
#define F_A1    (F_A0 + 32 * PITCH)
#define F_B0    (F_A1 + 32 * PITCH)
#define F_B1    (F_B0 + 32 * PITCH)
#define SMEM_FLOATS (F_B1 + 32 * PITCH)    // 37504
#define SMEM_BYTES  (SMEM_FLOATS * 4)      // 150016

__global__ __launch_bounds__(NTHREADS, 1)
void fused_mma_kernel(const float* __restrict__ sph,
                      const float* __restrict__ m,
                      float* __restrict__ out) {
    extern __shared__ float sm[];
    int* s_trip = (int*)sm;

    const int tid  = threadIdx.x;
    const int warp = tid >> 5, lane = tid & 31;
    const int mtile = blockIdx.x >> 1;
    const int kh    = blockIdx.x & 1;
    const int n0    = mtile * MT;

    // stage triplet ids (clamped)
    for (int x = tid; x < MT * KMAX; x += NTHREADS) {
        int edge = n0 + (x >> 4); if (edge >= NE) edge = NE - 1;
        int tr = d_trip[edge * KMAX + (x & 15)];
        s_trip[x] = (tr < 0) ? 0 : (tr >= NTRIP ? NTRIP - 1 : tr);
    }
    // stage sph tile: s_sph[n*113 + s*16 + k]
    for (int x = tid; x < MT * 112; x += NTHREADS) {
        int n_ = x / 112, y = x - n_ * 112;
        int eg = n0 + n_; if (eg >= NE) eg = NE - 1;
        sm[F_SPH + n_ * SPH_P + y] = sph[(size_t)eg * 112 + y];
    }
    __syncthreads();

    // thread identity: edge n (0..127), e-quad h (0..3)
    const int n = tid & 127, h = tid >> 7;

    ull sk[NSPH][2];     // sumk[s][e-pair] for this thread's 4 e's

    // phase1 for local e-group gl (e = (kh*4+gl)*16 + h*4 .. +4)
    auto phase1 = [&](int gl) {
        #pragma unroll
        for (int s = 0; s < NSPH; ++s) { sk[s][0] = 0ULL; sk[s][1] = 0ULL; }
        const int ebase = (kh * 4 + gl) * 16 + h * 4;
        const float* sphrow = sm + F_SPH + n * SPH_P;
        #pragma unroll
        for (int k = 0; k < KMAX; ++k) {
            float4 mv = *(const float4*)(m + (size_t)s_trip[n * KMAX + k] * EMB + ebase);
            ull mp0 = pack2(mv.x, mv.y), mp1 = pack2(mv.z, mv.w);
            #pragma unroll
            for (int s = 0; s < NSPH; ++s) {
                float sv = sphrow[s * 16 + k];
                ull s2 = pack2(sv, sv);
                sk[s][0] = ffma2(s2, mp0, sk[s][0]);
                sk[s][1] = ffma2(s2, mp1, sk[s][1]);
            }
        }
    };

    // buildA for chunk cn into buffer cn&1; rb buffer cn&1 holds 14 planes [r][n]
    auto buildA = [&](int cn) {
        float* As = sm + ((cn & 1) ? F_A1 : F_A0);
        const float* rb = sm + F_RB + (cn & 1) * 1792;
        #pragma unroll
        for (int i2 = 0; i2 < 2; ++i2) {
            ull a0, a1;
            {
                float v = rb[(i2 * 7) * 128 + n];
                ull rr = pack2(v, v);
                a0 = mul2(rr, sk[0][0]); a1 = mul2(rr, sk[0][1]);
            }
            #pragma unroll
            for (int s = 1; s < NSPH; ++s) {
                float v = rb[(i2 * 7 + s) * 128 + n];
                ull rr = pack2(v, v);
                a0 = ffma2(rr, sk[s][0], a0);
                a1 = ffma2(rr, sk[s][1], a1);
            }
            float f0, f1, f2, f3;
            unpack2(a0, f0, f1); unpack2(a1, f2, f3);
            int kb = i2 * 16 + h * 4;
            As[(kb + 0) * PITCH + n] = __uint_as_float(f2tf32(f0));
            As[(kb + 1) * PITCH + n] = __uint_as_float(f2tf32(f1));
            As[(kb + 2) * PITCH + n] = __uint_as_float(f2tf32(f2));
            As[(kb + 3) * PITCH + n] = __uint_as_float(f2tf32(f3));
        }
    };

    // async copies for chunk cn
    auto copyB = [&](int cn) {
        const int cg = kh * CHUNKS + cn;
        const float* src = d_Wimg + (size_t)cg * 4096;
        uint32_t Bs = smem_u32(sm + ((cn & 1) ? F_B1 : F_B0));
        #pragma unroll
        for (int jj = 0; jj < 2; ++jj) {
            int fidx = tid + 512 * jj;
            int row = fidx >> 5, c4 = fidx & 31;
            cp_async16(Bs + (uint32_t)(row * PITCH + c4 * 4) * 4, src + fidx * 4);
        }
    };
    auto stageRb = [&](int cn) {
        // rows 14j..14j+13 of d_rbfT, 128 floats starting at n0
        const int j = cn & 31;
        uint32_t dst = smem_u32(sm + F_RB + (cn & 1) * 1792);
        if (tid < 448) {
            int row = tid >> 5, c4 = tid & 31;
            const float* src = d_rbfT + (size_t)(14 * j + row) * NE + n0 + c4 * 4;
            cp_async16(dst + (uint32_t)(row * 128 + c4 * 4) * 4, src);
        }
    };

    phase1(0);
    stageRb(0); CP_COMMIT(); CP_WAIT0();
    __syncthreads();          // rb visible to all
    buildA(0);
    copyB(0); CP_COMMIT(); CP_WAIT0();
    __syncthreads();

    // ---- mma mainloop ----
    const int wm = (warp >> 2) * 32, wn = (warp & 3) * 32;
    const int q = lane >> 2, r = lane & 3;

    float acc[2][4][4];
    #pragma unroll
    for (int mi = 0; mi < 2; ++mi)
        #pragma unroll
        for (int ni = 0; ni < 4; ++ni)
            #pragma unroll
            for (int v = 0; v < 4; ++v) acc[mi][ni][v] = 0.f;

    for (int c = 0; c < CHUNKS; ++c) {
        const int p = c & 1;
        if (c + 1 < CHUNKS) { copyB(c + 1); stageRb(c + 1); CP_COMMIT(); }
        if ((c & 31) == 31 && c + 1 < CHUNKS) phase1((c + 1) >> 5);

        const uint32_t* Au = (const uint32_t*)(sm + (p ? F_A1 : F_A0));
        const uint32_t* Bu = (const uint32_t*)(sm + (p ? F_B1 : F_B0));
        #pragma unroll
        for (int ks = 0; ks < 4; ++ks) {
            const int kb = ks * 8;
            uint32_t a[2][4];
            #pragma unroll
            for (int mi = 0; mi < 2; ++mi) {
                int base = (kb + r) * PITCH + wm + mi * 16 + q;
                a[mi][0] = Au[base];
                a[mi][1] = Au[base + 8];
                a[mi][2] = Au[base + 4 * PITCH];
                a[mi][3] = Au[base + 4 * PITCH + 8];
            }
            #pragma unroll
            for (int ni = 0; ni < 4; ++ni) {
                uint32_t b0 = Bu[(kb + r) * PITCH + wn + ni * 8 + q];
                uint32_t b1 = Bu[(kb + r + 4) * PITCH + wn + ni * 8 + q];
                #pragma unroll
                for (int mi = 0; mi < 2; ++mi)
                    MMA_TF32(acc[mi][ni], a[mi], b0, b1);
            }
        }

        CP_WAIT0();            // rb(c+1) ready for buildA
        __syncthreads();       // A-buffer (c+1)&1 free (its MMA done)
        if (c + 1 < CHUNKS) buildA(c + 1);
        __syncthreads();       // A(c+1), B(c+1) visible before next MMA
    }

    // ---- epilogue: atomic add partial (split-K) ----
    #pragma unroll
    for (int mi = 0; mi < 2; ++mi) {
        int row0 = n0 + wm + mi * 16 + q;
        int row1 = row0 + 8;
        #pragma unroll
        for (int ni = 0; ni < 4; ++ni) {
            int col = wn + ni * 8 + 2 * r;
            if (row0 < NE) {
                atomicAdd(&out[(size_t)row0 * NOUT + col],     acc[mi][ni][0]);
                atomicAdd(&out[(size_t)row0 * NOUT + col + 1], acc[mi][ni][1]);
            }
            if (row1 < NE) {
                atomicAdd(&out[(size_t)row1 * NOUT + col],     acc[mi][ni][2]);
                atomicAdd(&out[(size_t)row1 * NOUT + col + 1], acc[mi][ni][3]);
            }
        }
    }
}

extern "C" void kernel_launch(void* const* d_in, const int* in_sizes, int n_in,
                              void* d_out, int out_size) {
    const float *rbf = 0, *sph = 0, *m = 0, *weight = 0;
    const void *idr = 0, *kix = 0;
    for (int i = 0; i < n_in; ++i) {
        long long sz = in_sizes[i];
        if      (sz == (long long)NE * INTERM * NSPH)  rbf = (const float*)d_in[i];
        else if (sz == (long long)NE * NSPH * KMAX)    sph = (const float*)d_in[i];
        else if (sz == (long long)NTRIP * EMB)         m = (const float*)d_in[i];
        else if (sz == (long long)EMB * INTERM * NOUT) weight = (const float*)d_in[i];
        else if (sz == (long long)NTRIP) { if (!idr) idr = d_in[i]; else kix = d_in[i]; }
    }
    float* out = (float*)d_out;

    cudaFuncSetAttribute(fused_mma_kernel,
                         cudaFuncAttributeMaxDynamicSharedMemorySize, SMEM_BYTES);

    detect_kernel<<<1, 256>>>(idr, kix, NTRIP);
    build_idx_kernel<<<(NTRIP + 255) / 256, 256>>>(idr, kix, NTRIP);
    prep_kernel<<<NB_WIMG + NB_RBFT + NB_ZERO, 256>>>(weight, rbf, out);
    fused_mma_kernel<<<NTILES_M * KSPLIT, NTHREADS, SMEM_BYTES>>>(sph, m, out);
}

// round 9
// speedup vs baseline: 2.4260x; 1.1096x over previous
#include <cuda_runtime.h>
#include <cstdint>

#define NE      20000
#define KMAX    16
#define NTRIP   (NE * KMAX)
#define EMB     128
#define INTERM  64
#define NSPH    7
#define NOUT    128
#define MT      128
#define NTHREADS 512
#define NTILES_M 157
#define KSPLIT  2
#define CHUNKS  128             // per CTA; chunk = 2 i-values x 16 e  (K=32)
#define PITCH   136             // A/B smem row pitch (floats)

typedef unsigned long long ull;

// ---------------- persistent device scratch ----------------
__device__ int   d_trip[NTRIP];
__device__ int   d_is64;
__device__ float d_Wimg[256 * 4096];            // tf32 B tiles
__device__ float d_rbfT[INTERM * NSPH * NE];    // rbf transposed [i][s][e]
__device__ float d_sumk[(size_t)NE * NSPH * EMB];  // 72 MB: phase-1 result [edge][s][e]

// ---------------- helpers ----------------
__device__ __forceinline__ uint32_t smem_u32(const void* p) {
    uint32_t a;
    asm("{ .reg .u64 t; cvta.to.shared.u64 t, %1; cvt.u32.u64 %0, t; }" : "=r"(a) : "l"(p));
    return a;
}
__device__ __forceinline__ ull pack2(float x, float y) {
    ull r; asm("mov.b64 %0, {%1,%2};" : "=l"(r) : "f"(x), "f"(y)); return r;
}
__device__ __forceinline__ void unpack2(ull v, float& x, float& y) {
    asm("mov.b64 {%0,%1}, %2;" : "=f"(x), "=f"(y) : "l"(v));
}
__device__ __forceinline__ ull ffma2(ull a, ull b, ull c) {
    ull d; asm("fma.rn.f32x2 %0, %1, %2, %3;" : "=l"(d) : "l"(a), "l"(b), "l"(c)); return d;
}
__device__ __forceinline__ ull mul2(ull a, ull b) {
    ull d; asm("mul.rn.f32x2 %0, %1, %2;" : "=l"(d) : "l"(a), "l"(b)); return d;
}
__device__ __forceinline__ uint32_t f2tf32(float f) {
    uint32_t v; asm("cvt.rna.tf32.f32 %0, %1;" : "=r"(v) : "f"(f)); return v;
}
__device__ __forceinline__ void cp_async16(uint32_t dst, const void* src) {
    asm volatile("cp.async.cg.shared.global [%0], [%1], 16;" :: "r"(dst), "l"(src) : "memory");
}
#define CP_COMMIT() asm volatile("cp.async.commit_group;" ::: "memory")
#define CP_WAIT0()  asm volatile("cp.async.wait_group 0;" ::: "memory")

#define MMA_TF32(d, a, b0, b1)                                                 \
    asm volatile("mma.sync.aligned.m16n8k8.row.col.f32.tf32.tf32.f32 "         \
        "{%0,%1,%2,%3}, {%4,%5,%6,%7}, {%8,%9}, {%0,%1,%2,%3};"                \
        : "+f"((d)[0]), "+f"((d)[1]), "+f"((d)[2]), "+f"((d)[3])               \
        : "r"((a)[0]), "r"((a)[1]), "r"((a)[2]), "r"((a)[3]),                  \
          "r"(b0), "r"(b1))

// ---------------- prologue kernels ----------------
__global__ void detect_kernel(const void* idr, const void* kix, int n) {
    __shared__ int bad;
    if (threadIdx.x == 0) bad = 0;
    __syncthreads();
    int cnt = n < 2048 ? n : 2048;
    const long long* a = (const long long*)idr;
    const long long* b = (const long long*)kix;
    for (int t = threadIdx.x; t < cnt; t += blockDim.x) {
        long long v = a[t], w = b[t];
        if (v < 0 || v >= NE || w < 0 || w >= KMAX) bad = 1;
    }
    __syncthreads();
    if (threadIdx.x == 0) d_is64 = bad ? 0 : 1;
}

__global__ void build_idx_kernel(const void* idr, const void* kix, int n) {
    int t = blockIdx.x * blockDim.x + threadIdx.x;
    if (t >= n) return;
    int e, k;
    if (d_is64) {
        e = (int)((const long long*)idr)[t];
        k = (int)((const long long*)kix)[t];
    } else {
        e = ((const int*)idr)[t];
        k = ((const int*)kix)[t];
    }
    if (e >= 0 && e < NE && k >= 0 && k < KMAX) d_trip[e * KMAX + k] = t;
}

// blocks [0,256): Wimg; [256,+2188): rbfT; [+2500): zero out
#define NB_WIMG 256
#define NB_RBFT 2188
#define NB_ZERO 2500
__global__ void prep_kernel(const float* __restrict__ W,
                            const float* __restrict__ rbf,
                            float* __restrict__ out) {
    int bid = blockIdx.x;
    if (bid < NB_WIMG) {
        int cg = bid;
        int kh = cg >> 7, c = cg & 127;
        int g = kh * 4 + (c >> 5), j = c & 31;
        float* dst = d_Wimg + (size_t)cg * 4096;
        #pragma unroll
        for (int jj = 0; jj < 16; ++jj) {
            int idx = threadIdx.x + 256 * jj;
            int k = idx >> 7, o = idx & 127;
            int e = g * 16 + (k & 15);
            int i = 2 * j + (k >> 4);
            float v = W[(size_t)e * (INTERM * NOUT) + i * NOUT + o];
            dst[idx] = __uint_as_float(f2tf32(v));
        }
    } else if (bid < NB_WIMG + NB_RBFT) {
        int base = (bid - NB_WIMG) * 4096;
        #pragma unroll
        for (int jj = 0; jj < 16; ++jj) {
            int idx = base + jj * 256 + threadIdx.x;
            if (idx < INTERM * NSPH * NE) {
                int row = idx / NE, e = idx - row * NE;
                d_rbfT[idx] = rbf[(size_t)e * (INTERM * NSPH) + row];
            }
        }
    } else {
        int i = (bid - NB_WIMG - NB_RBFT) * 256 + threadIdx.x;
        if (i < NE * NOUT / 4)
            ((float4*)out)[i] = make_float4(0.f, 0.f, 0.f, 0.f);
    }
}

// phase-1 precompute: one edge per block. Same accumulation order as before.
__global__ __launch_bounds__(128, 8)
void sumk_kernel(const float* __restrict__ sph, const float* __restrict__ m) {
    __shared__ float ssph[112];
    __shared__ int strip[16];
    const int edge = blockIdx.x;
    const int e = threadIdx.x;
    if (e < 112) ssph[e] = sph[(size_t)edge * 112 + e];
    if (e < 16) {
        int tr = d_trip[edge * KMAX + e];
        strip[e] = (tr < 0) ? 0 : (tr >= NTRIP ? NTRIP - 1 : tr);
    }
    __syncthreads();
    float acc[NSPH];
    #pragma unroll
    for (int s = 0; s < NSPH; ++s) acc[s] = 0.f;
    #pragma unroll
    for (int k = 0; k < KMAX; ++k) {
        float mv = m[(size_t)strip[k] * EMB + e];
        #pragma unroll
        for (int s = 0; s < NSPH; ++s) acc[s] = fmaf(ssph[s * 16 + k], mv, acc[s]);
    }
    #pragma unroll
    for (int s = 0; s < NSPH; ++s)
        d_sumk[(size_t)edge * (NSPH * EMB) + s * EMB + e] = acc[s];
}

// ---------------- main fused kernel ----------------
// smem float offsets
#define F_RB    0                          // 2 x 1792
#define F_A0    3584
#define F_A1    (F_A0 + 32 * PITCH)
#define F_B0    (F_A1 + 32 * PITCH)
#define F_B1    (F_B0 + 32 * PITCH)
#define SMEM_FLOATS (F_B1 + 32 * PITCH)    // 20992
#define SMEM_BYTES  (SMEM_FLOATS * 4)      // 83968

__global__ __launch_bounds__(NTHREADS, 1)
void fused_mma_kernel(const float* __restrict__ m_unused,
                      float* __restrict__ out) {
    extern __shared__ float sm[];

    const int tid  = threadIdx.x;
    const int warp = tid >> 5, lane = tid & 31;
    const int mtile = blockIdx.x >> 1;
    const int kh    = blockIdx.x & 1;
    const int n0    = mtile * MT;

    // thread identity: edge n (0..127), e-quad h (0..3)
    const int n = tid & 127, h = tid >> 7;
    int nglob = n0 + n; if (nglob >= NE) nglob = NE - 1;

    ull sk[NSPH][2];     // sumk[s][e-pair] for this thread's 4 e's

    // load sk for local group gl from precomputed d_sumk (7 LDG.128)
    auto loadSk = [&](int gl) {
        const int ebase = (kh * 4 + gl) * 16 + h * 4;
        const float* p = d_sumk + (size_t)nglob * (NSPH * EMB) + ebase;
        #pragma unroll
        for (int s = 0; s < NSPH; ++s) {
            float4 v = *(const float4*)(p + s * EMB);
            sk[s][0] = pack2(v.x, v.y);
            sk[s][1] = pack2(v.z, v.w);
        }
    };

    // buildA for chunk cn into buffer cn&1; rb buffer cn&1 holds 14 planes [r][n]
    auto buildA = [&](int cn) {
        float* As = sm + ((cn & 1) ? F_A1 : F_A0);
        const float* rb = sm + F_RB + (cn & 1) * 1792;
        #pragma unroll
        for (int i2 = 0; i2 < 2; ++i2) {
            ull a0, a1;
            {
                float v = rb[(i2 * 7) * 128 + n];
                ull rr = pack2(v, v);
                a0 = mul2(rr, sk[0][0]); a1 = mul2(rr, sk[0][1]);
            }
            #pragma unroll
            for (int s = 1; s < NSPH; ++s) {
                float v = rb[(i2 * 7 + s) * 128 + n];
                ull rr = pack2(v, v);
                a0 = ffma2(rr, sk[s][0], a0);
                a1 = ffma2(rr, sk[s][1], a1);
            }
            float f0, f1, f2, f3;
            unpack2(a0, f0, f1); unpack2(a1, f2, f3);
            int kb = i2 * 16 + h * 4;
            As[(kb + 0) * PITCH + n] = __uint_as_float(f2tf32(f0));
            As[(kb + 1) * PITCH + n] = __uint_as_float(f2tf32(f1));
            As[(kb + 2) * PITCH + n] = __uint_as_float(f2tf32(f2));
            As[(kb + 3) * PITCH + n] = __uint_as_float(f2tf32(f3));
        }
    };

    auto copyB = [&](int cn) {
        const int cg = kh * CHUNKS + cn;
        const float* src = d_Wimg + (size_t)cg * 4096;
        uint32_t Bs = smem_u32(sm + ((cn & 1) ? F_B1 : F_B0));
        #pragma unroll
        for (int jj = 0; jj < 2; ++jj) {
            int fidx = tid + 512 * jj;
            int row = fidx >> 5, c4 = fidx & 31;
            cp_async16(Bs + (uint32_t)(row * PITCH + c4 * 4) * 4, src + fidx * 4);
        }
    };
    auto stageRb = [&](int cn) {
        const int j = cn & 31;
        uint32_t dst = smem_u32(sm + F_RB + (cn & 1) * 1792);
        if (tid < 448) {
            int row = tid >> 5, c4 = tid & 31;
            const float* src = d_rbfT + (size_t)(14 * j + row) * NE + n0 + c4 * 4;
            cp_async16(dst + (uint32_t)(row * 128 + c4 * 4) * 4, src);
        }
    };

    // ---- prologue ----
    loadSk(0);
    stageRb(0); stageRb(1); CP_COMMIT(); CP_WAIT0();
    __syncthreads();
    buildA(0);
    copyB(0); CP_COMMIT(); CP_WAIT0();
    __syncthreads();

    // ---- mma mainloop: ONE barrier per chunk ----
    const int wm = (warp >> 2) * 32, wn = (warp & 3) * 32;
    const int q = lane >> 2, r = lane & 3;

    float acc[2][4][4];
    #pragma unroll
    for (int mi = 0; mi < 2; ++mi)
        #pragma unroll
        for (int ni = 0; ni < 4; ++ni)
            #pragma unroll
            for (int v = 0; v < 4; ++v) acc[mi][ni][v] = 0.f;

    for (int c = 0; c < CHUNKS; ++c) {
        const int p = c & 1;
        if (c + 1 < CHUNKS) {
            copyB(c + 1);
            if (c + 2 < CHUNKS) stageRb(c + 2);
            CP_COMMIT();
            if (((c + 1) & 31) == 0) loadSk((c + 1) >> 5);
            buildA(c + 1);             // writes A buf (c+1)&1; overlaps MMA(c)
        }

        const uint32_t* Au = (const uint32_t*)(sm + (p ? F_A1 : F_A0));
        const uint32_t* Bu = (const uint32_t*)(sm + (p ? F_B1 : F_B0));
        #pragma unroll
        for (int ks = 0; ks < 4; ++ks) {
            const int kb = ks * 8;
            uint32_t a[2][4];
            #pragma unroll
            for (int mi = 0; mi < 2; ++mi) {
                int base = (kb + r) * PITCH + wm + mi * 16 + q;
                a[mi][0] = Au[base];
                a[mi][1] = Au[base + 8];
                a[mi][2] = Au[base + 4 * PITCH];
                a[mi][3] = Au[base + 4 * PITCH + 8];
            }
            #pragma unroll
            for (int ni = 0; ni < 4; ++ni) {
                uint32_t b0 = Bu[(kb + r) * PITCH + wn + ni * 8 + q];
                uint32_t b1 = Bu[(kb + r + 4) * PITCH + wn + ni * 8 + q];
                #pragma unroll
                for (int mi = 0; mi < 2; ++mi)
                    MMA_TF32(acc[mi][ni], a[mi], b0, b1);
            }
        }

        CP_WAIT0();            // B(c+1) + rb(c+2) arrived
        __syncthreads();       // A(c+1)/B(c+1) visible; buffers of c now free
    }

    // ---- epilogue: atomic add partial (split-K) ----
    #pragma unroll
    for (int mi = 0; mi < 2; ++mi) {
        int row0 = n0 + wm + mi * 16 + q;
        int row1 = row0 + 8;
        #pragma unroll
        for (int ni = 0; ni < 4; ++ni) {
            int col = wn + ni * 8 + 2 * r;
            if (row0 < NE) {
                atomicAdd(&out[(size_t)row0 * NOUT + col],     acc[mi][ni][0]);
                atomicAdd(&out[(size_t)row0 * NOUT + col + 1], acc[mi][ni][1]);
            }
            if (row1 < NE) {
                atomicAdd(&out[(size_t)row1 * NOUT + col],     acc[mi][ni][2]);
                atomicAdd(&out[(size_t)row1 * NOUT + col + 1], acc[mi][ni][3]);
            }
        }
    }
}

extern "C" void kernel_launch(void* const* d_in, const int* in_sizes, int n_in,
                              void* d_out, int out_size) {
    const float *rbf = 0, *sph = 0, *m = 0, *weight = 0;
    const void *idr = 0, *kix = 0;
    for (int i = 0; i < n_in; ++i) {
        long long sz = in_sizes[i];
        if      (sz == (long long)NE * INTERM * NSPH)  rbf = (const float*)d_in[i];
        else if (sz == (long long)NE * NSPH * KMAX)    sph = (const float*)d_in[i];
        else if (sz == (long long)NTRIP * EMB)         m = (const float*)d_in[i];
        else if (sz == (long long)EMB * INTERM * NOUT) weight = (const float*)d_in[i];
        else if (sz == (long long)NTRIP) { if (!idr) idr = d_in[i]; else kix = d_in[i]; }
    }
    float* out = (float*)d_out;

    cudaFuncSetAttribute(fused_mma_kernel,
                         cudaFuncAttributeMaxDynamicSharedMemorySize, SMEM_BYTES);

    detect_kernel<<<1, 256>>>(idr, kix, NTRIP);
    build_idx_kernel<<<(NTRIP + 255) / 256, 256>>>(idr, kix, NTRIP);
    prep_kernel<<<NB_WIMG + NB_RBFT + NB_ZERO, 256>>>(weight, rbf, out);
    sumk_kernel<<<NE, 128>>>(sph, m);
    fused_mma_kernel<<<NTILES_M * KSPLIT, NTHREADS, SMEM_BYTES>>>(m, out);
}

// round 10
// speedup vs baseline: 3.1855x; 1.3131x over previous
#include <cuda_runtime.h>
#include <cstdint>

#define NE      20000
#define KMAX    16
#define NTRIP   (NE * KMAX)
#define EMB     128
#define INTERM  64
#define NSPH    7
#define NOUT    128
#define MT      128
#define NTHREADS 512
#define CHUNKS  128             // chunks per K-half (chunk = 2 i x 16 e, K=32)
#define PITCH   136             // A/B smem row pitch (floats)

// grid: 304 full units + 80 tail units (5 mtiles x 2 kh x 8 kq of 16 chunks)
#define NB_FULL 304
#define NB_TAIL 80
#define GRID_MAIN (NB_FULL + NB_TAIL)

typedef unsigned long long ull;

// ---------------- persistent device scratch ----------------
__device__ int   d_trip[NTRIP];
__device__ int   d_is64;
__device__ float d_Wimg[256 * 4096];            // tf32 B tiles
__device__ float d_rbfT[INTERM * NSPH * NE];    // rbf transposed [i][s][e]
__device__ float d_sumk[(size_t)NE * NSPH * EMB];  // 72 MB: phase-1 result [edge][s][e]

// ---------------- helpers ----------------
__device__ __forceinline__ uint32_t smem_u32(const void* p) {
    uint32_t a;
    asm("{ .reg .u64 t; cvta.to.shared.u64 t, %1; cvt.u32.u64 %0, t; }" : "=r"(a) : "l"(p));
    return a;
}
__device__ __forceinline__ ull pack2(float x, float y) {
    ull r; asm("mov.b64 %0, {%1,%2};" : "=l"(r) : "f"(x), "f"(y)); return r;
}
__device__ __forceinline__ void unpack2(ull v, float& x, float& y) {
    asm("mov.b64 {%0,%1}, %2;" : "=f"(x), "=f"(y) : "l"(v));
}
__device__ __forceinline__ ull ffma2(ull a, ull b, ull c) {
    ull d; asm("fma.rn.f32x2 %0, %1, %2, %3;" : "=l"(d) : "l"(a), "l"(b), "l"(c)); return d;
}
__device__ __forceinline__ ull mul2(ull a, ull b) {
    ull d; asm("mul.rn.f32x2 %0, %1, %2;" : "=l"(d) : "l"(a), "l"(b)); return d;
}
__device__ __forceinline__ uint32_t f2tf32(float f) {
    uint32_t v; asm("cvt.rna.tf32.f32 %0, %1;" : "=r"(v) : "f"(f)); return v;
}
__device__ __forceinline__ void cp_async16(uint32_t dst, const void* src) {
    asm volatile("cp.async.cg.shared.global [%0], [%1], 16;" :: "r"(dst), "l"(src) : "memory");
}
#define CP_COMMIT() asm volatile("cp.async.commit_group;" ::: "memory")
#define CP_WAIT0()  asm volatile("cp.async.wait_group 0;" ::: "memory")

#define MMA_TF32(d, a, b0, b1)                                                 \
    asm volatile("mma.sync.aligned.m16n8k8.row.col.f32.tf32.tf32.f32 "         \
        "{%0,%1,%2,%3}, {%4,%5,%6,%7}, {%8,%9}, {%0,%1,%2,%3};"                \
        : "+f"((d)[0]), "+f"((d)[1]), "+f"((d)[2]), "+f"((d)[3])               \
        : "r"((a)[0]), "r"((a)[1]), "r"((a)[2]), "r"((a)[3]),                  \
          "r"(b0), "r"(b1))

// ---------------- prologue kernels ----------------
__global__ void detect_kernel(const void* idr, const void* kix, int n) {
    __shared__ int bad;
    if (threadIdx.x == 0) bad = 0;
    __syncthreads();
    int cnt = n < 2048 ? n : 2048;
    const long long* a = (const long long*)idr;
    const long long* b = (const long long*)kix;
    for (int t = threadIdx.x; t < cnt; t += blockDim.x) {
        long long v = a[t], w = b[t];
        if (v < 0 || v >= NE || w < 0 || w >= KMAX) bad = 1;
    }
    __syncthreads();
    if (threadIdx.x == 0) d_is64 = bad ? 0 : 1;
}

__global__ void build_idx_kernel(const void* idr, const void* kix, int n) {
    int t = blockIdx.x * blockDim.x + threadIdx.x;
    if (t >= n) return;
    int e, k;
    if (d_is64) {
        e = (int)((const long long*)idr)[t];
        k = (int)((const long long*)kix)[t];
    } else {
        e = ((const int*)idr)[t];
        k = ((const int*)kix)[t];
    }
    if (e >= 0 && e < NE && k >= 0 && k < KMAX) d_trip[e * KMAX + k] = t;
}

// blocks [0,256): Wimg; [256,+2188): rbfT; [+2500): zero out
#define NB_WIMG 256
#define NB_RBFT 2188
#define NB_ZERO 2500
__global__ void prep_kernel(const float* __restrict__ W,
                            const float* __restrict__ rbf,
                            float* __restrict__ out) {
    int bid = blockIdx.x;
    if (bid < NB_WIMG) {
        int cg = bid;
        int kh = cg >> 7, c = cg & 127;
        int g = kh * 4 + (c >> 5), j = c & 31;
        float* dst = d_Wimg + (size_t)cg * 4096;
        #pragma unroll
        for (int jj = 0; jj < 16; ++jj) {
            int idx = threadIdx.x + 256 * jj;
            int k = idx >> 7, o = idx & 127;
            int e = g * 16 + (k & 15);
            int i = 2 * j + (k >> 4);
            float v = W[(size_t)e * (INTERM * NOUT) + i * NOUT + o];
            dst[idx] = __uint_as_float(f2tf32(v));
        }
    } else if (bid < NB_WIMG + NB_RBFT) {
        int base = (bid - NB_WIMG) * 4096;
        #pragma unroll
        for (int jj = 0; jj < 16; ++jj) {
            int idx = base + jj * 256 + threadIdx.x;
            if (idx < INTERM * NSPH * NE) {
                int row = idx / NE, e = idx - row * NE;
                d_rbfT[idx] = rbf[(size_t)e * (INTERM * NSPH) + row];
            }
        }
    } else {
        int i = (bid - NB_WIMG - NB_RBFT) * 256 + threadIdx.x;
        if (i < NE * NOUT / 4)
            ((float4*)out)[i] = make_float4(0.f, 0.f, 0.f, 0.f);
    }
}

// phase-1 precompute: one edge per block. Same accumulation order as before.
__global__ __launch_bounds__(128, 8)
void sumk_kernel(const float* __restrict__ sph, const float* __restrict__ m) {
    __shared__ float ssph[112];
    __shared__ int strip[16];
    const int edge = blockIdx.x;
    const int e = threadIdx.x;
    if (e < 112) ssph[e] = sph[(size_t)edge * 112 + e];
    if (e < 16) {
        int tr = d_trip[edge * KMAX + e];
        strip[e] = (tr < 0) ? 0 : (tr >= NTRIP ? NTRIP - 1 : tr);
    }
    __syncthreads();
    float acc[NSPH];
    #pragma unroll
    for (int s = 0; s < NSPH; ++s) acc[s] = 0.f;
    #pragma unroll
    for (int k = 0; k < KMAX; ++k) {
        float mv = m[(size_t)strip[k] * EMB + e];
        #pragma unroll
        for (int s = 0; s < NSPH; ++s) acc[s] = fmaf(ssph[s * 16 + k], mv, acc[s]);
    }
    #pragma unroll
    for (int s = 0; s < NSPH; ++s)
        d_sumk[(size_t)edge * (NSPH * EMB) + s * EMB + e] = acc[s];
}

// ---------------- main fused kernel ----------------
// smem float offsets
#define F_RB    0                          // 2 x 1792
#define F_A0    3584
#define F_A1    (F_A0 + 32 * PITCH)
#define F_B0    (F_A1 + 32 * PITCH)
#define F_B1    (F_B0 + 32 * PITCH)
#define SMEM_FLOATS (F_B1 + 32 * PITCH)    // 20992
#define SMEM_BYTES  (SMEM_FLOATS * 4)      // 83968

__global__ __launch_bounds__(NTHREADS, 1)
void fused_mma_kernel(float* __restrict__ out) {
    extern __shared__ float sm[];

    const int tid  = threadIdx.x;
    const int warp = tid >> 5, lane = tid & 31;
    const int bid  = blockIdx.x;

    // ---- work descriptor: full units first, tail split last ----
    int mtile, kh, c0, nch;
    if (bid < NB_FULL) {
        mtile = bid >> 1; kh = bid & 1; c0 = 0; nch = CHUNKS;
    } else {
        int t = bid - NB_FULL;          // 0..79
        int unit = t >> 3;              // 0..9
        mtile = 152 + (unit >> 1);
        kh = unit & 1;
        c0 = (t & 7) * 16;
        nch = 16;
    }
    const int cend = c0 + nch;
    const int n0 = mtile * MT;

    // thread identity: edge n (0..127), e-quad h (0..3)
    const int n = tid & 127, h = tid >> 7;
    int nglob = n0 + n; if (nglob >= NE) nglob = NE - 1;

    ull sk[NSPH][2];     // sumk[s][e-pair] for this thread's 4 e's

    auto loadSk = [&](int gl) {
        const int ebase = (kh * 4 + gl) * 16 + h * 4;
        const float* p = d_sumk + (size_t)nglob * (NSPH * EMB) + ebase;
        #pragma unroll
        for (int s = 0; s < NSPH; ++s) {
            float4 v = *(const float4*)(p + s * EMB);
            sk[s][0] = pack2(v.x, v.y);
            sk[s][1] = pack2(v.z, v.w);
        }
    };

    auto buildA = [&](int cn) {
        float* As = sm + ((cn & 1) ? F_A1 : F_A0);
        const float* rb = sm + F_RB + (cn & 1) * 1792;
        #pragma unroll
        for (int i2 = 0; i2 < 2; ++i2) {
            ull a0, a1;
            {
                float v = rb[(i2 * 7) * 128 + n];
                ull rr = pack2(v, v);
                a0 = mul2(rr, sk[0][0]); a1 = mul2(rr, sk[0][1]);
            }
            #pragma unroll
            for (int s = 1; s < NSPH; ++s) {
                float v = rb[(i2 * 7 + s) * 128 + n];
                ull rr = pack2(v, v);
                a0 = ffma2(rr, sk[s][0], a0);
                a1 = ffma2(rr, sk[s][1], a1);
            }
            float f0, f1, f2, f3;
            unpack2(a0, f0, f1); unpack2(a1, f2, f3);
            int kb = i2 * 16 + h * 4;
            As[(kb + 0) * PITCH + n] = __uint_as_float(f2tf32(f0));
            As[(kb + 1) * PITCH + n] = __uint_as_float(f2tf32(f1));
            As[(kb + 2) * PITCH + n] = __uint_as_float(f2tf32(f2));
            As[(kb + 3) * PITCH + n] = __uint_as_float(f2tf32(f3));
        }
    };

    auto copyB = [&](int cn) {
        const int cg = kh * CHUNKS + cn;
        const float* src = d_Wimg + (size_t)cg * 4096;
        uint32_t Bs = smem_u32(sm + ((cn & 1) ? F_B1 : F_B0));
        #pragma unroll
        for (int jj = 0; jj < 2; ++jj) {
            int fidx = tid + 512 * jj;
            int row = fidx >> 5, c4 = fidx & 31;
            cp_async16(Bs + (uint32_t)(row * PITCH + c4 * 4) * 4, src + fidx * 4);
        }
    };
    auto stageRb = [&](int cn) {
        const int j = cn & 31;
        uint32_t dst = smem_u32(sm + F_RB + (cn & 1) * 1792);
        if (tid < 448) {
            int row = tid >> 5, c4 = tid & 31;
            const float* src = d_rbfT + (size_t)(14 * j + row) * NE + n0 + c4 * 4;
            cp_async16(dst + (uint32_t)(row * 128 + c4 * 4) * 4, src);
        }
    };

    // ---- prologue ----
    loadSk(c0 >> 5);
    stageRb(c0); if (c0 + 1 < cend) stageRb(c0 + 1);
    CP_COMMIT(); CP_WAIT0();
    __syncthreads();
    buildA(c0);
    copyB(c0); CP_COMMIT(); CP_WAIT0();
    __syncthreads();

    // ---- mma mainloop: ONE barrier per chunk ----
    const int wm = (warp >> 2) * 32, wn = (warp & 3) * 32;
    const int q = lane >> 2, r = lane & 3;

    float acc[2][4][4];
    #pragma unroll
    for (int mi = 0; mi < 2; ++mi)
        #pragma unroll
        for (int ni = 0; ni < 4; ++ni)
            #pragma unroll
            for (int v = 0; v < 4; ++v) acc[mi][ni][v] = 0.f;

    for (int c = c0; c < cend; ++c) {
        const int p = c & 1;
        if (c + 1 < cend) {
            copyB(c + 1);
            if (c + 2 < cend) stageRb(c + 2);
            CP_COMMIT();
            if (((c + 1) & 31) == 0) loadSk((c + 1) >> 5);
            buildA(c + 1);             // writes A buf (c+1)&1; overlaps MMA(c)
        }

        const uint32_t* Au = (const uint32_t*)(sm + (p ? F_A1 : F_A0));
        const uint32_t* Bu = (const uint32_t*)(sm + (p ? F_B1 : F_B0));
        #pragma unroll
        for (int ks = 0; ks < 4; ++ks) {
            const int kb = ks * 8;
            uint32_t a[2][4];
            #pragma unroll
            for (int mi = 0; mi < 2; ++mi) {
                int base = (kb + r) * PITCH + wm + mi * 16 + q;
                a[mi][0] = Au[base];
                a[mi][1] = Au[base + 8];
                a[mi][2] = Au[base + 4 * PITCH];
                a[mi][3] = Au[base + 4 * PITCH + 8];
            }
            #pragma unroll
            for (int ni = 0; ni < 4; ++ni) {
                uint32_t b0 = Bu[(kb + r) * PITCH + wn + ni * 8 + q];
                uint32_t b1 = Bu[(kb + r + 4) * PITCH + wn + ni * 8 + q];
                #pragma unroll
                for (int mi = 0; mi < 2; ++mi)
                    MMA_TF32(acc[mi][ni], a[mi], b0, b1);
            }
        }

        CP_WAIT0();            // B(c+1) + rb(c+2) arrived
        __syncthreads();       // A(c+1)/B(c+1) visible; buffers of c now free
    }

    // ---- epilogue: atomic add partial (split-K) ----
    #pragma unroll
    for (int mi = 0; mi < 2; ++mi) {
        int row0 = n0 + wm + mi * 16 + q;
        int row1 = row0 + 8;
        #pragma unroll
        for (int ni = 0; ni < 4; ++ni) {
            int col = wn + ni * 8 + 2 * r;
            if (row0 < NE) {
                atomicAdd(&out[(size_t)row0 * NOUT + col],     acc[mi][ni][0]);
                atomicAdd(&out[(size_t)row0 * NOUT + col + 1], acc[mi][ni][1]);
            }
            if (row1 < NE) {
                atomicAdd(&out[(size_t)row1 * NOUT + col],     acc[mi][ni][2]);
                atomicAdd(&out[(size_t)row1 * NOUT + col + 1], acc[mi][ni][3]);
            }
        }
    }
}

extern "C" void kernel_launch(void* const* d_in, const int* in_sizes, int n_in,
                              void* d_out, int out_size) {
    const float *rbf = 0, *sph = 0, *m = 0, *weight = 0;
    const void *idr = 0, *kix = 0;
    for (int i = 0; i < n_in; ++i) {
        long long sz = in_sizes[i];
        if      (sz == (long long)NE * INTERM * NSPH)  rbf = (const float*)d_in[i];
        else if (sz == (long long)NE * NSPH * KMAX)    sph = (const float*)d_in[i];
        else if (sz == (long long)NTRIP * EMB)         m = (const float*)d_in[i];
        else if (sz == (long long)EMB * INTERM * NOUT) weight = (const float*)d_in[i];
        else if (sz == (long long)NTRIP) { if (!idr) idr = d_in[i]; else kix = d_in[i]; }
    }
    float* out = (float*)d_out;

    cudaFuncSetAttribute(fused_mma_kernel,
                         cudaFuncAttributeMaxDynamicSharedMemorySize, SMEM_BYTES);

    detect_kernel<<<1, 256>>>(idr, kix, NTRIP);
    build_idx_kernel<<<(NTRIP + 255) / 256, 256>>>(idr, kix, NTRIP);
    prep_kernel<<<NB_WIMG + NB_RBFT + NB_ZERO, 256>>>(weight, rbf, out);
    sumk_kernel<<<NE, 128>>>(sph, m);
    fused_mma_kernel<<<GRID_MAIN, NTHREADS, SMEM_BYTES>>>(out);
}

// round 11
// speedup vs baseline: 3.3014x; 1.0364x over previous
#include <cuda_runtime.h>
#include <cstdint>

#define NE      20000
#define KMAX    16
#define NTRIP   (NE * KMAX)
#define EMB     128
#define INTERM  64
#define NSPH    7
#define NOUT    128
#define MT      128
#define NTHREADS 512
#define CHUNKS  64              // chunks per K-half (chunk = 4 i x 16 e, K=64)
#define PITCH   136             // A/B smem row pitch (floats)

// grid: 304 full units + 80 tail units (5 mtiles x 2 kh x 8 units of 8 chunks)
#define NB_FULL 304
#define NB_TAIL 80
#define GRID_MAIN (NB_FULL + NB_TAIL)

typedef unsigned long long ull;

// ---------------- persistent device scratch ----------------
__device__ int   d_trip[NTRIP];
__device__ int   d_is64;
__device__ float d_Wimg[256 * 4096];            // tf32 B tiles [32k x 128n] each
__device__ float d_rbfT[INTERM * NSPH * NE];    // rbf transposed [i][s][e]
__device__ float d_sumk[(size_t)NE * NSPH * EMB];  // phase-1 result [edge][s][e]

// ---------------- helpers ----------------
__device__ __forceinline__ uint32_t smem_u32(const void* p) {
    uint32_t a;
    asm("{ .reg .u64 t; cvta.to.shared.u64 t, %1; cvt.u32.u64 %0, t; }" : "=r"(a) : "l"(p));
    return a;
}
__device__ __forceinline__ ull pack2(float x, float y) {
    ull r; asm("mov.b64 %0, {%1,%2};" : "=l"(r) : "f"(x), "f"(y)); return r;
}
__device__ __forceinline__ void unpack2(ull v, float& x, float& y) {
    asm("mov.b64 {%0,%1}, %2;" : "=f"(x), "=f"(y) : "l"(v));
}
__device__ __forceinline__ ull ffma2(ull a, ull b, ull c) {
    ull d; asm("fma.rn.f32x2 %0, %1, %2, %3;" : "=l"(d) : "l"(a), "l"(b), "l"(c)); return d;
}
__device__ __forceinline__ ull mul2(ull a, ull b) {
    ull d; asm("mul.rn.f32x2 %0, %1, %2;" : "=l"(d) : "l"(a), "l"(b)); return d;
}
__device__ __forceinline__ uint32_t f2tf32(float f) {
    uint32_t v; asm("cvt.rna.tf32.f32 %0, %1;" : "=r"(v) : "f"(f)); return v;
}
__device__ __forceinline__ void cp_async16(uint32_t dst, const void* src) {
    asm volatile("cp.async.cg.shared.global [%0], [%1], 16;" :: "r"(dst), "l"(src) : "memory");
}
#define CP_COMMIT() asm volatile("cp.async.commit_group;" ::: "memory")
#define CP_WAIT0()  asm volatile("cp.async.wait_group 0;" ::: "memory")

#define MMA_TF32(d, a, b0, b1)                                                 \
    asm volatile("mma.sync.aligned.m16n8k8.row.col.f32.tf32.tf32.f32 "         \
        "{%0,%1,%2,%3}, {%4,%5,%6,%7}, {%8,%9}, {%0,%1,%2,%3};"                \
        : "+f"((d)[0]), "+f"((d)[1]), "+f"((d)[2]), "+f"((d)[3])               \
        : "r"((a)[0]), "r"((a)[1]), "r"((a)[2]), "r"((a)[3]),                  \
          "r"(b0), "r"(b1))

// ---------------- prologue kernels ----------------
__global__ void detect_kernel(const void* idr, const void* kix, int n) {
    __shared__ int bad;
    if (threadIdx.x == 0) bad = 0;
    __syncthreads();
    int cnt = n < 2048 ? n : 2048;
    const long long* a = (const long long*)idr;
    const long long* b = (const long long*)kix;
    for (int t = threadIdx.x; t < cnt; t += blockDim.x) {
        long long v = a[t], w = b[t];
        if (v < 0 || v >= NE || w < 0 || w >= KMAX) bad = 1;
    }
    __syncthreads();
    if (threadIdx.x == 0) d_is64 = bad ? 0 : 1;
}

__global__ void build_idx_kernel(const void* idr, const void* kix, int n) {
    int t = blockIdx.x * blockDim.x + threadIdx.x;
    if (t >= n) return;
    int e, k;
    if (d_is64) {
        e = (int)((const long long*)idr)[t];
        k = (int)((const long long*)kix)[t];
    } else {
        e = ((const int*)idr)[t];
        k = ((const int*)kix)[t];
    }
    if (e >= 0 && e < NE && k >= 0 && k < KMAX) d_trip[e * KMAX + k] = t;
}

// merged prep: sumk first (long pole), then Wimg, rbfT, zero-out
#define NB_SUMK 10000
#define NB_WIMG 256
#define NB_RBFT 2188
#define NB_ZERO 2500
#define GRID_PREP (NB_SUMK + NB_WIMG + NB_RBFT + NB_ZERO)
__global__ __launch_bounds__(256)
void prep_kernel(const float* __restrict__ W,
                 const float* __restrict__ rbf,
                 const float* __restrict__ sph,
                 const float* __restrict__ m,
                 float* __restrict__ out) {
    int bid = blockIdx.x;
    if (bid < NB_SUMK) {
        // sumk for 2 edges per block; same accumulation order as before
        __shared__ float ssph[2][112];
        __shared__ int strip[2][16];
        const int which = threadIdx.x >> 7;
        const int e = threadIdx.x & 127;
        const int edge = bid * 2 + which;
        if (e < 112) ssph[which][e] = sph[(size_t)edge * 112 + e];
        if (e < 16) {
            int tr = d_trip[edge * KMAX + e];
            strip[which][e] = (tr < 0) ? 0 : (tr >= NTRIP ? NTRIP - 1 : tr);
        }
        __syncthreads();
        float acc[NSPH];
        #pragma unroll
        for (int s = 0; s < NSPH; ++s) acc[s] = 0.f;
        #pragma unroll
        for (int k = 0; k < KMAX; ++k) {
            float mv = m[(size_t)strip[which][k] * EMB + e];
            #pragma unroll
            for (int s = 0; s < NSPH; ++s) acc[s] = fmaf(ssph[which][s * 16 + k], mv, acc[s]);
        }
        #pragma unroll
        for (int s = 0; s < NSPH; ++s)
            d_sumk[(size_t)edge * (NSPH * EMB) + s * EMB + e] = acc[s];
    } else if (bid < NB_SUMK + NB_WIMG) {
        int cg = bid - NB_SUMK;
        int kh = cg >> 7, c = cg & 127;
        int g = kh * 4 + (c >> 5), j = c & 31;
        float* dst = d_Wimg + (size_t)cg * 4096;
        #pragma unroll
        for (int jj = 0; jj < 16; ++jj) {
            int idx = threadIdx.x + 256 * jj;
            int k = idx >> 7, o = idx & 127;
            int e = g * 16 + (k & 15);
            int i = 2 * j + (k >> 4);
            float v = W[(size_t)e * (INTERM * NOUT) + i * NOUT + o];
            dst[idx] = __uint_as_float(f2tf32(v));
        }
    } else if (bid < NB_SUMK + NB_WIMG + NB_RBFT) {
        int base = (bid - NB_SUMK - NB_WIMG) * 4096;
        #pragma unroll
        for (int jj = 0; jj < 16; ++jj) {
            int idx = base + jj * 256 + threadIdx.x;
            if (idx < INTERM * NSPH * NE) {
                int row = idx / NE, e = idx - row * NE;
                d_rbfT[idx] = rbf[(size_t)e * (INTERM * NSPH) + row];
            }
        }
    } else {
        int i = (bid - NB_SUMK - NB_WIMG - NB_RBFT) * 256 + threadIdx.x;
        if (i < NE * NOUT / 4)
            ((float4*)out)[i] = make_float4(0.f, 0.f, 0.f, 0.f);
    }
}

// ---------------- main fused kernel ----------------
// smem float offsets (chunk = K=64: A/B tiles 64 x PITCH, rb 28 x 128)
#define F_RB    0                          // 2 x 3584
#define F_A0    7168
#define F_A1    (F_A0 + 64 * PITCH)
#define F_B0    (F_A1 + 64 * PITCH)
#define F_B1    (F_B0 + 64 * PITCH)
#define SMEM_FLOATS (F_B1 + 64 * PITCH)    // 41984
#define SMEM_BYTES  (SMEM_FLOATS * 4)      // 167936

__global__ __launch_bounds__(NTHREADS, 1)
void fused_mma_kernel(float* __restrict__ out) {
    extern __shared__ float sm[];

    const int tid  = threadIdx.x;
    const int warp = tid >> 5, lane = tid & 31;
    const int bid  = blockIdx.x;

    // ---- work descriptor ----
    int mtile, kh, c0, nch;
    if (bid < NB_FULL) {
        mtile = bid >> 1; kh = bid & 1; c0 = 0; nch = CHUNKS;
    } else {
        int t = bid - NB_FULL;          // 0..79
        int unit = t >> 3;              // 0..9
        mtile = 152 + (unit >> 1);
        kh = unit & 1;
        c0 = (t & 7) * 8;
        nch = 8;
    }
    const int cend = c0 + nch;
    const int n0 = mtile * MT;

    // thread identity: edge n (0..127), e-quad h (0..3)
    const int n = tid & 127, h = tid >> 7;
    int nglob = n0 + n; if (nglob >= NE) nglob = NE - 1;

    ull sk[NSPH][2];     // sumk[s][e-pair] for this thread's 4 e's

    auto loadSk = [&](int gl) {
        const int ebase = (kh * 4 + gl) * 16 + h * 4;
        const float* p = d_sumk + (size_t)nglob * (NSPH * EMB) + ebase;
        #pragma unroll
        for (int s = 0; s < NSPH; ++s) {
            float4 v = *(const float4*)(p + s * EMB);
            sk[s][0] = pack2(v.x, v.y);
            sk[s][1] = pack2(v.z, v.w);
        }
    };

    // buildA for chunk cn: rows kk = i2*16 + h*4 + (0..3), i2 = 0..3
    auto buildA = [&](int cn) {
        float* As = sm + ((cn & 1) ? F_A1 : F_A0);
        const float* rb = sm + F_RB + (cn & 1) * 3584;
        #pragma unroll
        for (int i2 = 0; i2 < 4; ++i2) {
            ull a0, a1;
            {
                float v = rb[(i2 * 7) * 128 + n];
                ull rr = pack2(v, v);
                a0 = mul2(rr, sk[0][0]); a1 = mul2(rr, sk[0][1]);
            }
            #pragma unroll
            for (int s = 1; s < NSPH; ++s) {
                float v = rb[(i2 * 7 + s) * 128 + n];
                ull rr = pack2(v, v);
                a0 = ffma2(rr, sk[s][0], a0);
                a1 = ffma2(rr, sk[s][1], a1);
            }
            float f0, f1, f2, f3;
            unpack2(a0, f0, f1); unpack2(a1, f2, f3);
            int kb = i2 * 16 + h * 4;
            As[(kb + 0) * PITCH + n] = __uint_as_float(f2tf32(f0));
            As[(kb + 1) * PITCH + n] = __uint_as_float(f2tf32(f1));
            As[(kb + 2) * PITCH + n] = __uint_as_float(f2tf32(f2));
            As[(kb + 3) * PITCH + n] = __uint_as_float(f2tf32(f3));
        }
    };

    // B copy: two consecutive Wimg tiles (8192 floats) -> 64 rows with pitch
    auto copyB = [&](int cn) {
        const float* src = d_Wimg + (size_t)(kh * 128 + cn * 2) * 4096;
        uint32_t Bs = smem_u32(sm + ((cn & 1) ? F_B1 : F_B0));
        #pragma unroll
        for (int jj = 0; jj < 4; ++jj) {
            int fidx = tid + 512 * jj;          // float4 index, 0..2047
            int row = fidx >> 5, c4 = fidx & 31;
            cp_async16(Bs + (uint32_t)(row * PITCH + c4 * 4) * 4, src + fidx * 4);
        }
    };
    // rb: 28 rows (i in [4j, 4j+4), s 0..6) x 128 edges
    auto stageRb = [&](int cn) {
        const int j = cn & 15;
        uint32_t dst = smem_u32(sm + F_RB + (cn & 1) * 3584);
        if (tid < 448) {
            #pragma unroll
            for (int jj = 0; jj < 2; ++jj) {
                int idx = tid + 448 * jj;       // float4 index, 0..895
                int row = idx >> 5, c4 = idx & 31;
                const float* src = d_rbfT + (size_t)(28 * j + row) * NE + n0 + c4 * 4;
                cp_async16(dst + (uint32_t)(row * 128 + c4 * 4) * 4, src);
            }
        }
    };

    // ---- prologue ----
    loadSk(c0 >> 4);
    stageRb(c0); stageRb(c0 + 1);
    CP_COMMIT(); CP_WAIT0();
    __syncthreads();
    buildA(c0);
    copyB(c0); CP_COMMIT(); CP_WAIT0();
    __syncthreads();

    // ---- mma mainloop: ONE barrier per K=64 chunk ----
    const int wm = (warp >> 2) * 32, wn = (warp & 3) * 32;
    const int q = lane >> 2, r = lane & 3;

    float acc[2][4][4];
    #pragma unroll
    for (int mi = 0; mi < 2; ++mi)
        #pragma unroll
        for (int ni = 0; ni < 4; ++ni)
            #pragma unroll
            for (int v = 0; v < 4; ++v) acc[mi][ni][v] = 0.f;

    for (int c = c0; c < cend; ++c) {
        const int p = c & 1;
        if (c + 1 < cend) {
            copyB(c + 1);
            if (c + 2 < cend) stageRb(c + 2);
            CP_COMMIT();
            if (((c + 1) & 15) == 0) loadSk((c + 1) >> 4);
            buildA(c + 1);             // writes A buf (c+1)&1; overlaps MMA(c)
        }

        const uint32_t* Au = (const uint32_t*)(sm + (p ? F_A1 : F_A0));
        const uint32_t* Bu = (const uint32_t*)(sm + (p ? F_B1 : F_B0));
        #pragma unroll
        for (int ks = 0; ks < 8; ++ks) {
            const int kb = ks * 8;
            uint32_t a[2][4];
            #pragma unroll
            for (int mi = 0; mi < 2; ++mi) {
                int base = (kb + r) * PITCH + wm + mi * 16 + q;
                a[mi][0] = Au[base];
                a[mi][1] = Au[base + 8];
                a[mi][2] = Au[base + 4 * PITCH];
                a[mi][3] = Au[base + 4 * PITCH + 8];
            }
            #pragma unroll
            for (int ni = 0; ni < 4; ++ni) {
                uint32_t b0 = Bu[(kb + r) * PITCH + wn + ni * 8 + q];
                uint32_t b1 = Bu[(kb + r + 4) * PITCH + wn + ni * 8 + q];
                #pragma unroll
                for (int mi = 0; mi < 2; ++mi)
                    MMA_TF32(acc[mi][ni], a[mi], b0, b1);
            }
        }

        CP_WAIT0();            // B(c+1) + rb(c+2) arrived
        __syncthreads();       // A(c+1)/B(c+1) visible; buffers of c free
    }

    // ---- epilogue: atomic add partial (split-K) ----
    #pragma unroll
    for (int mi = 0; mi < 2; ++mi) {
        int row0 = n0 + wm + mi * 16 + q;
        int row1 = row0 + 8;
        #pragma unroll
        for (int ni = 0; ni < 4; ++ni) {
            int col = wn + ni * 8 + 2 * r;
            if (row0 < NE) {
                atomicAdd(&out[(size_t)row0 * NOUT + col],     acc[mi][ni][0]);
                atomicAdd(&out[(size_t)row0 * NOUT + col + 1], acc[mi][ni][1]);
            }
            if (row1 < NE) {
                atomicAdd(&out[(size_t)row1 * NOUT + col],     acc[mi][ni][2]);
                atomicAdd(&out[(size_t)row1 * NOUT + col + 1], acc[mi][ni][3]);
            }
        }
    }
}

extern "C" void kernel_launch(void* const* d_in, const int* in_sizes, int n_in,
                              void* d_out, int out_size) {
    const float *rbf = 0, *sph = 0, *m = 0, *weight = 0;
    const void *idr = 0, *kix = 0;
    for (int i = 0; i < n_in; ++i) {
        long long sz = in_sizes[i];
        if      (sz == (long long)NE * INTERM * NSPH)  rbf = (const float*)d_in[i];
        else if (sz == (long long)NE * NSPH * KMAX)    sph = (const float*)d_in[i];
        else if (sz == (long long)NTRIP * EMB)         m = (const float*)d_in[i];
        else if (sz == (long long)EMB * INTERM * NOUT) weight = (const float*)d_in[i];
        else if (sz == (long long)NTRIP) { if (!idr) idr = d_in[i]; else kix = d_in[i]; }
    }
    float* out = (float*)d_out;

    cudaFuncSetAttribute(fused_mma_kernel,
                         cudaFuncAttributeMaxDynamicSharedMemorySize, SMEM_BYTES);

    detect_kernel<<<1, 256>>>(idr, kix, NTRIP);
    build_idx_kernel<<<(NTRIP + 255) / 256, 256>>>(idr, kix, NTRIP);
    prep_kernel<<<GRID_PREP, 256>>>(weight, rbf, sph, m, out);
    fused_mma_kernel<<<GRID_MAIN, NTHREADS, SMEM_BYTES>>>(out);
}

// round 12
// speedup vs baseline: 3.4044x; 1.0312x over previous
#include <cuda_runtime.h>
#include <cstdint>

#define NE      20000
#define KMAX    16
#define NTRIP   (NE * KMAX)
#define EMB     128
#define INTERM  64
#define NSPH    7
#define NOUT    128
#define MT      128
#define NTHREADS 256
#define CHUNKS  64              // chunks per K-half (chunk = 4 i x 16 e, K=64)
#define PITCH   136             // A/B smem row pitch (floats)

// grid: 304 full units + 80 tail units (5 mtiles x 2 kh x 8 units of 8 chunks)
#define NB_FULL 304
#define NB_TAIL 80
#define GRID_MAIN (NB_FULL + NB_TAIL)

typedef unsigned long long ull;

// ---------------- persistent device scratch ----------------
__device__ int   d_trip[NTRIP];
__device__ int   d_is64;
__device__ float d_Wimg[256 * 4096];            // tf32 B tiles [32k x 128n] each
__device__ float d_rbfT[INTERM * NSPH * NE];    // rbf transposed [i][s][e]
__device__ float d_sumk[(size_t)NE * NSPH * EMB];  // phase-1 result [edge][s][e]

// ---------------- helpers ----------------
__device__ __forceinline__ uint32_t smem_u32(const void* p) {
    uint32_t a;
    asm("{ .reg .u64 t; cvta.to.shared.u64 t, %1; cvt.u32.u64 %0, t; }" : "=r"(a) : "l"(p));
    return a;
}
__device__ __forceinline__ ull pack2(float x, float y) {
    ull r; asm("mov.b64 %0, {%1,%2};" : "=l"(r) : "f"(x), "f"(y)); return r;
}
__device__ __forceinline__ void unpack2(ull v, float& x, float& y) {
    asm("mov.b64 {%0,%1}, %2;" : "=f"(x), "=f"(y) : "l"(v));
}
__device__ __forceinline__ ull ffma2(ull a, ull b, ull c) {
    ull d; asm("fma.rn.f32x2 %0, %1, %2, %3;" : "=l"(d) : "l"(a), "l"(b), "l"(c)); return d;
}
__device__ __forceinline__ ull mul2(ull a, ull b) {
    ull d; asm("mul.rn.f32x2 %0, %1, %2;" : "=l"(d) : "l"(a), "l"(b)); return d;
}
__device__ __forceinline__ uint32_t f2tf32(float f) {
    uint32_t v; asm("cvt.rna.tf32.f32 %0, %1;" : "=r"(v) : "f"(f)); return v;
}
__device__ __forceinline__ void cp_async16(uint32_t dst, const void* src) {
    asm volatile("cp.async.cg.shared.global [%0], [%1], 16;" :: "r"(dst), "l"(src) : "memory");
}
#define CP_COMMIT() asm volatile("cp.async.commit_group;" ::: "memory")
#define CP_WAIT0()  asm volatile("cp.async.wait_group 0;" ::: "memory")

#define MMA_TF32(d, a, b0, b1)                                                 \
    asm volatile("mma.sync.aligned.m16n8k8.row.col.f32.tf32.tf32.f32 "         \
        "{%0,%1,%2,%3}, {%4,%5,%6,%7}, {%8,%9}, {%0,%1,%2,%3};"                \
        : "+f"((d)[0]), "+f"((d)[1]), "+f"((d)[2]), "+f"((d)[3])               \
        : "r"((a)[0]), "r"((a)[1]), "r"((a)[2]), "r"((a)[3]),                  \
          "r"(b0), "r"(b1))

// ---------------- prologue kernels ----------------
__global__ void detect_kernel(const void* idr, const void* kix, int n) {
    __shared__ int bad;
    if (threadIdx.x == 0) bad = 0;
    __syncthreads();
    int cnt = n < 2048 ? n : 2048;
    const long long* a = (const long long*)idr;
    const long long* b = (const long long*)kix;
    for (int t = threadIdx.x; t < cnt; t += blockDim.x) {
        long long v = a[t], w = b[t];
        if (v < 0 || v >= NE || w < 0 || w >= KMAX) bad = 1;
    }
    __syncthreads();
    if (threadIdx.x == 0) d_is64 = bad ? 0 : 1;
}

__global__ void build_idx_kernel(const void* idr, const void* kix, int n) {
    int t = blockIdx.x * blockDim.x + threadIdx.x;
    if (t >= n) return;
    int e, k;
    if (d_is64) {
        e = (int)((const long long*)idr)[t];
        k = (int)((const long long*)kix)[t];
    } else {
        e = ((const int*)idr)[t];
        k = ((const int*)kix)[t];
    }
    if (e >= 0 && e < NE && k >= 0 && k < KMAX) d_trip[e * KMAX + k] = t;
}

// merged prep: sumk first (long pole), then Wimg, rbfT, zero-out
#define NB_SUMK 10000
#define NB_WIMG 256
#define NB_RBFT 2188
#define NB_ZERO 2500
#define GRID_PREP (NB_SUMK + NB_WIMG + NB_RBFT + NB_ZERO)
__global__ __launch_bounds__(256)
void prep_kernel(const float* __restrict__ W,
                 const float* __restrict__ rbf,
                 const float* __restrict__ sph,
                 const float* __restrict__ m,
                 float* __restrict__ out) {
    int bid = blockIdx.x;
    if (bid < NB_SUMK) {
        __shared__ float ssph[2][112];
        __shared__ int strip[2][16];
        const int which = threadIdx.x >> 7;
        const int e = threadIdx.x & 127;
        const int edge = bid * 2 + which;
        if (e < 112) ssph[which][e] = sph[(size_t)edge * 112 + e];
        if (e < 16) {
            int tr = d_trip[edge * KMAX + e];
            strip[which][e] = (tr < 0) ? 0 : (tr >= NTRIP ? NTRIP - 1 : tr);
        }
        __syncthreads();
        float acc[NSPH];
        #pragma unroll
        for (int s = 0; s < NSPH; ++s) acc[s] = 0.f;
        #pragma unroll
        for (int k = 0; k < KMAX; ++k) {
            float mv = m[(size_t)strip[which][k] * EMB + e];
            #pragma unroll
            for (int s = 0; s < NSPH; ++s) acc[s] = fmaf(ssph[which][s * 16 + k], mv, acc[s]);
        }
        #pragma unroll
        for (int s = 0; s < NSPH; ++s)
            d_sumk[(size_t)edge * (NSPH * EMB) + s * EMB + e] = acc[s];
    } else if (bid < NB_SUMK + NB_WIMG) {
        int cg = bid - NB_SUMK;
        int kh = cg >> 7, c = cg & 127;
        int g = kh * 4 + (c >> 5), j = c & 31;
        float* dst = d_Wimg + (size_t)cg * 4096;
        #pragma unroll
        for (int jj = 0; jj < 16; ++jj) {
            int idx = threadIdx.x + 256 * jj;
            int k = idx >> 7, o = idx & 127;
            int e = g * 16 + (k & 15);
            int i = 2 * j + (k >> 4);
            float v = W[(size_t)e * (INTERM * NOUT) + i * NOUT + o];
            dst[idx] = __uint_as_float(f2tf32(v));
        }
    } else if (bid < NB_SUMK + NB_WIMG + NB_RBFT) {
        int base = (bid - NB_SUMK - NB_WIMG) * 4096;
        #pragma unroll
        for (int jj = 0; jj < 16; ++jj) {
            int idx = base + jj * 256 + threadIdx.x;
            if (idx < INTERM * NSPH * NE) {
                int row = idx / NE, e = idx - row * NE;
                d_rbfT[idx] = rbf[(size_t)e * (INTERM * NSPH) + row];
            }
        }
    } else {
        int i = (bid - NB_SUMK - NB_WIMG - NB_RBFT) * 256 + threadIdx.x;
        if (i < NE * NOUT / 4)
            ((float4*)out)[i] = make_float4(0.f, 0.f, 0.f, 0.f);
    }
}

// ---------------- main fused kernel ----------------
// smem float offsets (chunk = K=64: A/B tiles 64 x PITCH, rb 28 x 128)
#define F_RB    0                          // 2 x 3584
#define F_A0    7168
#define F_A1    (F_A0 + 64 * PITCH)
#define F_B0    (F_A1 + 64 * PITCH)
#define F_B1    (F_B0 + 64 * PITCH)
#define SMEM_FLOATS (F_B1 + 64 * PITCH)    // 41984
#define SMEM_BYTES  (SMEM_FLOATS * 4)      // 167936

__global__ __launch_bounds__(NTHREADS, 1)
void fused_mma_kernel(float* __restrict__ out) {
    extern __shared__ float sm[];

    const int tid  = threadIdx.x;
    const int warp = tid >> 5, lane = tid & 31;
    const int bid  = blockIdx.x;

    // ---- work descriptor ----
    int mtile, kh, c0, nch;
    if (bid < NB_FULL) {
        mtile = bid >> 1; kh = bid & 1; c0 = 0; nch = CHUNKS;
    } else {
        int t = bid - NB_FULL;          // 0..79
        int unit = t >> 3;              // 0..9
        mtile = 152 + (unit >> 1);
        kh = unit & 1;
        c0 = (t & 7) * 8;
        nch = 8;
    }
    const int cend = c0 + nch;
    const int n0 = mtile * MT;

    // thread identity for A production: edge n (0..127), e-octet h2 (0..1)
    const int n = tid & 127, h2 = tid >> 7;
    int nglob = n0 + n; if (nglob >= NE) nglob = NE - 1;

    ull sk[2][NSPH][2];   // [hh][s][e-pair]; thread covers e-quads h = 2*h2 + hh

    auto loadSk = [&](int gl) {
        #pragma unroll
        for (int hh = 0; hh < 2; ++hh) {
            const int ebase = (kh * 4 + gl) * 16 + (2 * h2 + hh) * 4;
            const float* p = d_sumk + (size_t)nglob * (NSPH * EMB) + ebase;
            #pragma unroll
            for (int s = 0; s < NSPH; ++s) {
                float4 v = *(const float4*)(p + s * EMB);
                sk[hh][s][0] = pack2(v.x, v.y);
                sk[hh][s][1] = pack2(v.z, v.w);
            }
        }
    };

    // buildA for chunk cn: rows kk = i2*16 + (2*h2+hh)*4 + (0..3), i2 = 0..3
    auto buildA = [&](int cn) {
        float* As = sm + ((cn & 1) ? F_A1 : F_A0);
        const float* rb = sm + F_RB + (cn & 1) * 3584;
        #pragma unroll
        for (int i2 = 0; i2 < 4; ++i2) {
            ull rr[NSPH];
            #pragma unroll
            for (int s = 0; s < NSPH; ++s) {
                float v = rb[(i2 * 7 + s) * 128 + n];
                rr[s] = pack2(v, v);
            }
            #pragma unroll
            for (int hh = 0; hh < 2; ++hh) {
                ull a0 = mul2(rr[0], sk[hh][0][0]);
                ull a1 = mul2(rr[0], sk[hh][0][1]);
                #pragma unroll
                for (int s = 1; s < NSPH; ++s) {
                    a0 = ffma2(rr[s], sk[hh][s][0], a0);
                    a1 = ffma2(rr[s], sk[hh][s][1], a1);
                }
                float f0, f1, f2, f3;
                unpack2(a0, f0, f1); unpack2(a1, f2, f3);
                int kb = i2 * 16 + (2 * h2 + hh) * 4;
                As[(kb + 0) * PITCH + n] = __uint_as_float(f2tf32(f0));
                As[(kb + 1) * PITCH + n] = __uint_as_float(f2tf32(f1));
                As[(kb + 2) * PITCH + n] = __uint_as_float(f2tf32(f2));
                As[(kb + 3) * PITCH + n] = __uint_as_float(f2tf32(f3));
            }
        }
    };

    // B copy: two consecutive Wimg tiles (8192 floats) -> 64 rows with pitch
    auto copyB = [&](int cn) {
        const float* src = d_Wimg + (size_t)(kh * 128 + cn * 2) * 4096;
        uint32_t Bs = smem_u32(sm + ((cn & 1) ? F_B1 : F_B0));
        #pragma unroll
        for (int jj = 0; jj < 8; ++jj) {
            int fidx = tid + 256 * jj;          // float4 index, 0..2047
            int row = fidx >> 5, c4 = fidx & 31;
            cp_async16(Bs + (uint32_t)(row * PITCH + c4 * 4) * 4, src + fidx * 4);
        }
    };
    // rb: 28 rows (i in [4j, 4j+4), s 0..6) x 128 edges = 896 float4
    auto stageRb = [&](int cn) {
        const int j = cn & 15;
        uint32_t dst = smem_u32(sm + F_RB + (cn & 1) * 3584);
        #pragma unroll
        for (int jj = 0; jj < 4; ++jj) {
            int idx = tid + 256 * jj;           // float4 index
            if (idx < 896) {
                int row = idx >> 5, c4 = idx & 31;
                const float* src = d_rbfT + (size_t)(28 * j + row) * NE + n0 + c4 * 4;
                cp_async16(dst + (uint32_t)(row * 128 + c4 * 4) * 4, src);
            }
        }
    };

    // ---- prologue ----
    loadSk(c0 >> 4);
    stageRb(c0); stageRb(c0 + 1);
    CP_COMMIT(); CP_WAIT0();
    __syncthreads();
    buildA(c0);
    copyB(c0); CP_COMMIT(); CP_WAIT0();
    __syncthreads();

    // ---- mma mainloop: warp tile 64m x 32n, ONE barrier per K=64 chunk ----
    const int wm = (warp >> 2) * 64, wn = (warp & 3) * 32;
    const int q = lane >> 2, r = lane & 3;

    float acc[4][4][4];
    #pragma unroll
    for (int mi = 0; mi < 4; ++mi)
        #pragma unroll
        for (int ni = 0; ni < 4; ++ni)
            #pragma unroll
            for (int v = 0; v < 4; ++v) acc[mi][ni][v] = 0.f;

    for (int c = c0; c < cend; ++c) {
        const int p = c & 1;
        if (c + 1 < cend) {
            copyB(c + 1);
            if (c + 2 < cend) stageRb(c + 2);
            CP_COMMIT();
            if (((c + 1) & 15) == 0) loadSk((c + 1) >> 4);
            buildA(c + 1);             // writes A buf (c+1)&1; overlaps MMA(c)
        }

        const uint32_t* Au = (const uint32_t*)(sm + (p ? F_A1 : F_A0));
        const uint32_t* Bu = (const uint32_t*)(sm + (p ? F_B1 : F_B0));
        #pragma unroll
        for (int ks = 0; ks < 8; ++ks) {
            const int kb = ks * 8;
            uint32_t a[4][4];
            #pragma unroll
            for (int mi = 0; mi < 4; ++mi) {
                int base = (kb + r) * PITCH + wm + mi * 16 + q;
                a[mi][0] = Au[base];
                a[mi][1] = Au[base + 8];
                a[mi][2] = Au[base + 4 * PITCH];
                a[mi][3] = Au[base + 4 * PITCH + 8];
            }
            #pragma unroll
            for (int ni = 0; ni < 4; ++ni) {
                uint32_t b0 = Bu[(kb + r) * PITCH + wn + ni * 8 + q];
                uint32_t b1 = Bu[(kb + r + 4) * PITCH + wn + ni * 8 + q];
                #pragma unroll
                for (int mi = 0; mi < 4; ++mi)
                    MMA_TF32(acc[mi][ni], a[mi], b0, b1);
            }
        }

        CP_WAIT0();            // B(c+1) + rb(c+2) arrived
        __syncthreads();       // A(c+1)/B(c+1) visible; buffers of c free
    }

    // ---- epilogue: atomic add partial (split-K) ----
    #pragma unroll
    for (int mi = 0; mi < 4; ++mi) {
        int row0 = n0 + wm + mi * 16 + q;
        int row1 = row0 + 8;
        #pragma unroll
        for (int ni = 0; ni < 4; ++ni) {
            int col = wn + ni * 8 + 2 * r;
            if (row0 < NE) {
                atomicAdd(&out[(size_t)row0 * NOUT + col],     acc[mi][ni][0]);
                atomicAdd(&out[(size_t)row0 * NOUT + col + 1], acc[mi][ni][1]);
            }
            if (row1 < NE) {
                atomicAdd(&out[(size_t)row1 * NOUT + col],     acc[mi][ni][2]);
                atomicAdd(&out[(size_t)row1 * NOUT + col + 1], acc[mi][ni][3]);
            }
        }
    }
}

extern "C" void kernel_launch(void* const* d_in, const int* in_sizes, int n_in,
                              void* d_out, int out_size) {
    const float *rbf = 0, *sph = 0, *m = 0, *weight = 0;
    const void *idr = 0, *kix = 0;
    for (int i = 0; i < n_in; ++i) {
        long long sz = in_sizes[i];
        if      (sz == (long long)NE * INTERM * NSPH)  rbf = (const float*)d_in[i];
        else if (sz == (long long)NE * NSPH * KMAX)    sph = (const float*)d_in[i];
        else if (sz == (long long)NTRIP * EMB)         m = (const float*)d_in[i];
        else if (sz == (long long)EMB * INTERM * NOUT) weight = (const float*)d_in[i];
        else if (sz == (long long)NTRIP) { if (!idr) idr = d_in[i]; else kix = d_in[i]; }
    }
    float* out = (float*)d_out;

    cudaFuncSetAttribute(fused_mma_kernel,
                         cudaFuncAttributeMaxDynamicSharedMemorySize, SMEM_BYTES);

    detect_kernel<<<1, 256>>>(idr, kix, NTRIP);
    build_idx_kernel<<<(NTRIP + 255) / 256, 256>>>(idr, kix, NTRIP);
    prep_kernel<<<GRID_PREP, 256>>>(weight, rbf, sph, m, out);
    fused_mma_kernel<<<GRID_MAIN, NTHREADS, SMEM_BYTES>>>(out);
}

// round 13
// speedup vs baseline: 5.1734x; 1.5196x over previous
#include <cuda_runtime.h>
#include <cuda_fp16.h>
#include <cstdint>

#define NE      20000
#define KMAX    16
#define NTRIP   (NE * KMAX)
#define EMB     128
#define INTERM  64
#define NSPH    7
#define NOUT    128
#define MT      128
#define NTHREADS 256
#define CHUNKS  64              // chunks per K-half (chunk = 4 i x 16 e, K=64)
#define PITCH   136             // A/B smem row pitch (in uint32)

#define NB_FULL 304
#define NB_TAIL 80
#define GRID_MAIN (NB_FULL + NB_TAIL)

typedef unsigned long long ull;

// ---------------- persistent device scratch ----------------
__device__ int      d_trip[NTRIP];
__device__ int      d_is64;
__device__ uint32_t d_Wimg[128 * 4096];         // fp16x2 B tiles [32 kp x 128 o] per K=64 chunk
__device__ float    d_rbfT[INTERM * NSPH * NE]; // rbf transposed [i][s][e]
__device__ float    d_sumk[(size_t)NE * NSPH * EMB];

// ---------------- helpers ----------------
__device__ __forceinline__ uint32_t smem_u32(const void* p) {
    uint32_t a;
    asm("{ .reg .u64 t; cvta.to.shared.u64 t, %1; cvt.u32.u64 %0, t; }" : "=r"(a) : "l"(p));
    return a;
}
__device__ __forceinline__ ull pack2(float x, float y) {
    ull r; asm("mov.b64 %0, {%1,%2};" : "=l"(r) : "f"(x), "f"(y)); return r;
}
__device__ __forceinline__ void unpack2(ull v, float& x, float& y) {
    asm("mov.b64 {%0,%1}, %2;" : "=f"(x), "=f"(y) : "l"(v));
}
__device__ __forceinline__ ull ffma2(ull a, ull b, ull c) {
    ull d; asm("fma.rn.f32x2 %0, %1, %2, %3;" : "=l"(d) : "l"(a), "l"(b), "l"(c)); return d;
}
__device__ __forceinline__ ull mul2(ull a, ull b) {
    ull d; asm("mul.rn.f32x2 %0, %1, %2;" : "=l"(d) : "l"(a), "l"(b)); return d;
}
__device__ __forceinline__ uint32_t packh2(float lo, float hi) {
    __half2 h = __floats2half2_rn(lo, hi);
    return *(uint32_t*)&h;
}
__device__ __forceinline__ void cp_async16(uint32_t dst, const void* src) {
    asm volatile("cp.async.cg.shared.global [%0], [%1], 16;" :: "r"(dst), "l"(src) : "memory");
}
#define CP_COMMIT() asm volatile("cp.async.commit_group;" ::: "memory")
#define CP_WAIT0()  asm volatile("cp.async.wait_group 0;" ::: "memory")

#define MMA_F16(d, a, b0, b1)                                                  \
    asm volatile("mma.sync.aligned.m16n8k16.row.col.f32.f16.f16.f32 "          \
        "{%0,%1,%2,%3}, {%4,%5,%6,%7}, {%8,%9}, {%0,%1,%2,%3};"                \
        : "+f"((d)[0]), "+f"((d)[1]), "+f"((d)[2]), "+f"((d)[3])               \
        : "r"((a)[0]), "r"((a)[1]), "r"((a)[2]), "r"((a)[3]),                  \
          "r"(b0), "r"(b1))

// ---------------- prologue kernels ----------------
__global__ void detect_kernel(const void* idr, const void* kix, int n) {
    __shared__ int bad;
    if (threadIdx.x == 0) bad = 0;
    __syncthreads();
    int cnt = n < 2048 ? n : 2048;
    const long long* a = (const long long*)idr;
    const long long* b = (const long long*)kix;
    for (int t = threadIdx.x; t < cnt; t += blockDim.x) {
        long long v = a[t], w = b[t];
        if (v < 0 || v >= NE || w < 0 || w >= KMAX) bad = 1;
    }
    __syncthreads();
    if (threadIdx.x == 0) d_is64 = bad ? 0 : 1;
}

__global__ void build_idx_kernel(const void* idr, const void* kix, int n) {
    int t = blockIdx.x * blockDim.x + threadIdx.x;
    if (t >= n) return;
    int e, k;
    if (d_is64) {
        e = (int)((const long long*)idr)[t];
        k = (int)((const long long*)kix)[t];
    } else {
        e = ((const int*)idr)[t];
        k = ((const int*)kix)[t];
    }
    if (e >= 0 && e < NE && k >= 0 && k < KMAX) d_trip[e * KMAX + k] = t;
}

// merged prep: sumk, Wimg(fp16), rbfT (tiled transpose), zero-out
#define NB_SUMK 10000
#define NB_WIMG 128
#define NB_RBFT 8750            // 14 x 625 tiles of 32x32
#define NB_ZERO 2500
#define GRID_PREP (NB_SUMK + NB_WIMG + NB_RBFT + NB_ZERO)
__global__ __launch_bounds__(256)
void prep_kernel(const float* __restrict__ W,
                 const float* __restrict__ rbf,
                 const float* __restrict__ sph,
                 const float* __restrict__ m,
                 float* __restrict__ out) {
    __shared__ float tile[32][33];
    __shared__ float ssph[2][112];
    __shared__ int strip[2][16];
    int bid = blockIdx.x;
    if (bid < NB_SUMK) {
        const int which = threadIdx.x >> 7;
        const int e = threadIdx.x & 127;
        const int edge = bid * 2 + which;
        if (e < 112) ssph[which][e] = sph[(size_t)edge * 112 + e];
        if (e < 16) {
            int tr = d_trip[edge * KMAX + e];
            strip[which][e] = (tr < 0) ? 0 : (tr >= NTRIP ? NTRIP - 1 : tr);
        }
        __syncthreads();
        float acc[NSPH];
        #pragma unroll
        for (int s = 0; s < NSPH; ++s) acc[s] = 0.f;
        #pragma unroll
        for (int k = 0; k < KMAX; ++k) {
            float mv = m[(size_t)strip[which][k] * EMB + e];
            #pragma unroll
            for (int s = 0; s < NSPH; ++s) acc[s] = fmaf(ssph[which][s * 16 + k], mv, acc[s]);
        }
        #pragma unroll
        for (int s = 0; s < NSPH; ++s)
            d_sumk[(size_t)edge * (NSPH * EMB) + s * EMB + e] = acc[s];
    } else if (bid < NB_SUMK + NB_WIMG) {
        // fp16 B image for chunk cg: rows kp (kk pair), cols o
        int cg = bid - NB_SUMK;            // 0..127
        int kh = cg >> 6, c = cg & 63;
        uint32_t* dst = d_Wimg + (size_t)cg * 4096;
        #pragma unroll
        for (int jj = 0; jj < 16; ++jj) {
            int idx = threadIdx.x + 256 * jj;   // kp*128 + o
            int kp = idx >> 7, o = idx & 127;
            int e0 = (kh * 4 + (c >> 4)) * 16 + 2 * (kp & 7);
            int i  = 4 * (c & 15) + (kp >> 3);
            float v0 = W[(size_t)e0 * (INTERM * NOUT) + i * NOUT + o];
            float v1 = W[(size_t)(e0 + 1) * (INTERM * NOUT) + i * NOUT + o];
            dst[idx] = packh2(v0, v1);
        }
    } else if (bid < NB_SUMK + NB_WIMG + NB_RBFT) {
        // tiled transpose: rbf[e][c] -> d_rbfT[c][e], 32x32 tiles
        int t = bid - NB_SUMK - NB_WIMG;
        int tr_ = t / 625, te = t - tr_ * 625;
        int cc0 = tr_ * 32, ee0 = te * 32;
        #pragma unroll
        for (int jj = 0; jj < 4; ++jj) {
            int idx = threadIdx.x + 256 * jj;
            int le = idx >> 5, lc = idx & 31;
            tile[le][lc] = rbf[(size_t)(ee0 + le) * (INTERM * NSPH) + cc0 + lc];
        }
        __syncthreads();
        #pragma unroll
        for (int jj = 0; jj < 4; ++jj) {
            int idx = threadIdx.x + 256 * jj;
            int lc = idx >> 5, le = idx & 31;
            d_rbfT[(size_t)(cc0 + lc) * NE + ee0 + le] = tile[le][lc];
        }
    } else {
        int i = (bid - NB_SUMK - NB_WIMG - NB_RBFT) * 256 + threadIdx.x;
        if (i < NE * NOUT / 4)
            ((float4*)out)[i] = make_float4(0.f, 0.f, 0.f, 0.f);
    }
}

// ---------------- main fused kernel ----------------
// smem float offsets (fp16 tiles: 32 kp-rows x PITCH uint32)
#define F_RB    0                          // 2 x 3584 floats
#define F_A0    7168
#define F_A1    (F_A0 + 32 * PITCH)
#define F_B0    (F_A1 + 32 * PITCH)
#define F_B1    (F_B0 + 32 * PITCH)
#define SMEM_FLOATS (F_B1 + 32 * PITCH)    // 24576
#define SMEM_BYTES  (SMEM_FLOATS * 4)      // 98304

__global__ __launch_bounds__(NTHREADS, 1)
void fused_mma_kernel(float* __restrict__ out) {
    extern __shared__ float sm[];

    const int tid  = threadIdx.x;
    const int warp = tid >> 5, lane = tid & 31;
    const int bid  = blockIdx.x;

    // ---- work descriptor ----
    int mtile, kh, c0, nch;
    if (bid < NB_FULL) {
        mtile = bid >> 1; kh = bid & 1; c0 = 0; nch = CHUNKS;
    } else {
        int t = bid - NB_FULL;
        int unit = t >> 3;
        mtile = 152 + (unit >> 1);
        kh = unit & 1;
        c0 = (t & 7) * 8;
        nch = 8;
    }
    const int cend = c0 + nch;
    const int n0 = mtile * MT;

    const int n = tid & 127, h2 = tid >> 7;
    int nglob = n0 + n; if (nglob >= NE) nglob = NE - 1;

    ull sk[2][NSPH][2];

    auto loadSk = [&](int gl) {
        #pragma unroll
        for (int hh = 0; hh < 2; ++hh) {
            const int ebase = (kh * 4 + gl) * 16 + (2 * h2 + hh) * 4;
            const float* p = d_sumk + (size_t)nglob * (NSPH * EMB) + ebase;
            #pragma unroll
            for (int s = 0; s < NSPH; ++s) {
                float4 v = *(const float4*)(p + s * EMB);
                sk[hh][s][0] = pack2(v.x, v.y);
                sk[hh][s][1] = pack2(v.z, v.w);
            }
        }
    };

    // buildA: fp16 pairs over consecutive kk (= consecutive e, same i)
    auto buildA = [&](int cn) {
        uint32_t* As = (uint32_t*)(sm + ((cn & 1) ? F_A1 : F_A0));
        const float* rb = sm + F_RB + (cn & 1) * 3584;
        #pragma unroll
        for (int i2 = 0; i2 < 4; ++i2) {
            ull rr[NSPH];
            #pragma unroll
            for (int s = 0; s < NSPH; ++s) {
                float v = rb[(i2 * 7 + s) * 128 + n];
                rr[s] = pack2(v, v);
            }
            #pragma unroll
            for (int hh = 0; hh < 2; ++hh) {
                ull a0 = mul2(rr[0], sk[hh][0][0]);
                ull a1 = mul2(rr[0], sk[hh][0][1]);
                #pragma unroll
                for (int s = 1; s < NSPH; ++s) {
                    a0 = ffma2(rr[s], sk[hh][s][0], a0);
                    a1 = ffma2(rr[s], sk[hh][s][1], a1);
                }
                float f0, f1, f2, f3;
                unpack2(a0, f0, f1); unpack2(a1, f2, f3);
                int kp0 = i2 * 8 + (2 * h2 + hh) * 2;   // kk/2
                As[kp0 * PITCH + n]       = packh2(f0, f1);
                As[(kp0 + 1) * PITCH + n] = packh2(f2, f3);
            }
        }
    };

    // B copy: 4096 uint32 (16 KB) per chunk
    auto copyB = [&](int cn) {
        const uint32_t* src = d_Wimg + (size_t)(kh * 64 + cn) * 4096;
        uint32_t Bs = smem_u32(sm + ((cn & 1) ? F_B1 : F_B0));
        #pragma unroll
        for (int jj = 0; jj < 4; ++jj) {
            int fidx = tid + 256 * jj;          // uint4 index, 0..1023
            int row = fidx >> 5, c4 = fidx & 31;
            cp_async16(Bs + (uint32_t)(row * PITCH + c4 * 4) * 4, src + fidx * 4);
        }
    };
    auto stageRb = [&](int cn) {
        const int j = cn & 15;
        uint32_t dst = smem_u32(sm + F_RB + (cn & 1) * 3584);
        #pragma unroll
        for (int jj = 0; jj < 4; ++jj) {
            int idx = tid + 256 * jj;           // float4 index
            if (idx < 896) {
                int row = idx >> 5, c4 = idx & 31;
                const float* src = d_rbfT + (size_t)(28 * j + row) * NE + n0 + c4 * 4;
                cp_async16(dst + (uint32_t)(row * 128 + c4 * 4) * 4, src);
            }
        }
    };

    // ---- prologue ----
    loadSk(c0 >> 4);
    stageRb(c0); stageRb(c0 + 1);
    CP_COMMIT(); CP_WAIT0();
    __syncthreads();
    buildA(c0);
    copyB(c0); CP_COMMIT(); CP_WAIT0();
    __syncthreads();

    // ---- mma mainloop: warp tile 64m x 32n, fp16 k16, one barrier/chunk ----
    const int wm = (warp >> 2) * 64, wn = (warp & 3) * 32;
    const int q = lane >> 2, r = lane & 3;

    float acc[4][4][4];
    #pragma unroll
    for (int mi = 0; mi < 4; ++mi)
        #pragma unroll
        for (int ni = 0; ni < 4; ++ni)
            #pragma unroll
            for (int v = 0; v < 4; ++v) acc[mi][ni][v] = 0.f;

    for (int c = c0; c < cend; ++c) {
        const int p = c & 1;
        if (c + 1 < cend) {
            copyB(c + 1);
            if (c + 2 < cend) stageRb(c + 2);
            CP_COMMIT();
            if (((c + 1) & 15) == 0) loadSk((c + 1) >> 4);
            buildA(c + 1);
        }

        const uint32_t* Au = (const uint32_t*)(sm + (p ? F_A1 : F_A0));
        const uint32_t* Bu = (const uint32_t*)(sm + (p ? F_B1 : F_B0));
        #pragma unroll
        for (int ks = 0; ks < 4; ++ks) {
            const int kp = ks * 8;
            uint32_t a[4][4];
            #pragma unroll
            for (int mi = 0; mi < 4; ++mi) {
                int base = (kp + r) * PITCH + wm + mi * 16 + q;
                a[mi][0] = Au[base];
                a[mi][1] = Au[base + 8];
                a[mi][2] = Au[base + 4 * PITCH];
                a[mi][3] = Au[base + 4 * PITCH + 8];
            }
            #pragma unroll
            for (int ni = 0; ni < 4; ++ni) {
                uint32_t b0 = Bu[(kp + r) * PITCH + wn + ni * 8 + q];
                uint32_t b1 = Bu[(kp + r + 4) * PITCH + wn + ni * 8 + q];
                #pragma unroll
                for (int mi = 0; mi < 4; ++mi)
                    MMA_F16(acc[mi][ni], a[mi], b0, b1);
            }
        }

        CP_WAIT0();
        __syncthreads();
    }

    // ---- epilogue: atomic add partial (split-K) ----
    #pragma unroll
    for (int mi = 0; mi < 4; ++mi) {
        int row0 = n0 + wm + mi * 16 + q;
        int row1 = row0 + 8;
        #pragma unroll
        for (int ni = 0; ni < 4; ++ni) {
            int col = wn + ni * 8 + 2 * r;
            if (row0 < NE) {
                atomicAdd(&out[(size_t)row0 * NOUT + col],     acc[mi][ni][0]);
                atomicAdd(&out[(size_t)row0 * NOUT + col + 1], acc[mi][ni][1]);
            }
            if (row1 < NE) {
                atomicAdd(&out[(size_t)row1 * NOUT + col],     acc[mi][ni][2]);
                atomicAdd(&out[(size_t)row1 * NOUT + col + 1], acc[mi][ni][3]);
            }
        }
    }
}

extern "C" void kernel_launch(void* const* d_in, const int* in_sizes, int n_in,
                              void* d_out, int out_size) {
    const float *rbf = 0, *sph = 0, *m = 0, *weight = 0;
    const void *idr = 0, *kix = 0;
    for (int i = 0; i < n_in; ++i) {
        long long sz = in_sizes[i];
        if      (sz == (long long)NE * INTERM * NSPH)  rbf = (const float*)d_in[i];
        else if (sz == (long long)NE * NSPH * KMAX)    sph = (const float*)d_in[i];
        else if (sz == (long long)NTRIP * EMB)         m = (const float*)d_in[i];
        else if (sz == (long long)EMB * INTERM * NOUT) weight = (const float*)d_in[i];
        else if (sz == (long long)NTRIP) { if (!idr) idr = d_in[i]; else kix = d_in[i]; }
    }
    float* out = (float*)d_out;

    cudaFuncSetAttribute(fused_mma_kernel,
                         cudaFuncAttributeMaxDynamicSharedMemorySize, SMEM_BYTES);

    detect_kernel<<<1, 256>>>(idr, kix, NTRIP);
    build_idx_kernel<<<(NTRIP + 255) / 256, 256>>>(idr, kix, NTRIP);
    prep_kernel<<<GRID_PREP, 256>>>(weight, rbf, sph, m, out);
    fused_mma_kernel<<<GRID_MAIN, NTHREADS, SMEM_BYTES>>>(out);
}